// round 9
// baseline (speedup 1.0000x reference)
#include <cuda_runtime.h>
#include <cuda_bf16.h>
#include <cstdint>

constexpr int B  = 4;
constexpr int C  = 512;
constexpr int T  = 3;
constexpr int HW = 2304;   // 48*48
constexpr int N3 = 6912;   // 3*HW
constexpr int G  = 4;
constexpr int CG = C / G;  // 128
constexpr float EPS = 1e-6f;

typedef __nv_bfloat16  bf16;
typedef __nv_bfloat162 bf162;

// Scratch
__device__ bf16  gb_hnt[(size_t)B * N3 * C];   // normalized, transposed, bf16
__device__ float g_hnt1[(size_t)B * HW * C];   // t=1 slice, fp32 (q path)
__device__ float g_qt  [(size_t)B * HW * C];   // q fp32 (skip)
__device__ bf16  gb_qt [(size_t)B * HW * C];   // q bf16 (scores operand)
__device__ bf16  gb_kt [(size_t)B * N3 * C];   // k [m][c]
__device__ bf16  gb_v  [(size_t)B * C * N3];   // v [c][m]
__device__ bf16  gb_sc [(size_t)B * HW * N3];  // scores / attn [p][m]
__device__ bf16  gb_ot [(size_t)B * HW * C];   // attn out [p][c]
__device__ bf16  gb_kw[C * C], gb_vw[C * C], gb_pw[C * C];
__device__ float g_stats[2 * B * G];

__device__ __forceinline__ uint32_t smem_u32(const void* p) {
    return (uint32_t)__cvta_generic_to_shared(p);
}
#define CP_ASYNC16(sm, gm) \
    asm volatile("cp.async.ca.shared.global [%0], [%1], 16;" :: "r"(sm), "l"(gm))
#define CP_COMMIT asm volatile("cp.async.commit_group;")
#define CP_WAIT1  asm volatile("cp.async.wait_group 1;")
#define CP_WAIT0  asm volatile("cp.async.wait_group 0;")

__device__ __forceinline__ void ldm_x4(uint32_t* r, uint32_t addr) {
    asm volatile("ldmatrix.sync.aligned.m8n8.x4.shared.b16 {%0,%1,%2,%3}, [%4];"
        : "=r"(r[0]), "=r"(r[1]), "=r"(r[2]), "=r"(r[3]) : "r"(addr));
}
__device__ __forceinline__ void mma_bf16(float* c, const uint32_t* a, const uint32_t* b) {
    asm volatile("mma.sync.aligned.m16n8k16.row.col.f32.bf16.bf16.f32 "
        "{%0,%1,%2,%3}, {%4,%5,%6,%7}, {%8,%9}, {%0,%1,%2,%3};"
        : "+f"(c[0]), "+f"(c[1]), "+f"(c[2]), "+f"(c[3])
        : "r"(a[0]), "r"(a[1]), "r"(a[2]), "r"(a[3]), "r"(b[0]), "r"(b[1]));
}

// ---------------------------------------------------------------------------
// GroupNorm
// ---------------------------------------------------------------------------
__global__ void zero_stats_kernel() {
    if (threadIdx.x < 2 * B * G) g_stats[threadIdx.x] = 0.f;
}

__global__ void gn_stats_kernel(const float* __restrict__ x) {
    const int bg = blockIdx.x;
    const int b = bg >> 2, g = bg & 3;
    const int TOT4 = CG * T * HW / 4;
    const int PER  = TOT4 / 16;
    const int start = blockIdx.y * PER;

    float s = 0.f, ss = 0.f;
    for (int i = start + threadIdx.x; i < start + PER; i += blockDim.x) {
        int cl = i / (T * HW / 4);
        int r  = i - cl * (T * HW / 4);
        int t  = r / (HW / 4);
        int p4 = r - t * (HW / 4);
        float4 v = reinterpret_cast<const float4*>(x)[
            ((size_t)(t * B + b) * C + g * CG + cl) * (HW / 4) + p4];
        s  += v.x + v.y + v.z + v.w;
        ss += v.x * v.x + v.y * v.y + v.z * v.z + v.w * v.w;
    }
    __shared__ float rs[8], rss[8];
    #pragma unroll
    for (int o = 16; o; o >>= 1) {
        s  += __shfl_xor_sync(0xffffffffu, s, o);
        ss += __shfl_xor_sync(0xffffffffu, ss, o);
    }
    if ((threadIdx.x & 31) == 0) { rs[threadIdx.x >> 5] = s; rss[threadIdx.x >> 5] = ss; }
    __syncthreads();
    if (threadIdx.x == 0) {
        float a = 0.f, c = 0.f;
        #pragma unroll
        for (int i = 0; i < 8; i++) { a += rs[i]; c += rss[i]; }
        atomicAdd(&g_stats[2 * bg],     a);
        atomicAdd(&g_stats[2 * bg + 1], c);
    }
}

// normalize + affine + transpose -> gb_hnt (bf16); t=1 slice also fp32
__global__ void gn_apply_t_kernel(const float* __restrict__ x,
                                  const float* __restrict__ scale,
                                  const float* __restrict__ bias) {
    __shared__ float tile[32][33];
    const int bt = blockIdx.z;
    const int b = bt / T, t = bt - b * T;
    const int p0 = blockIdx.x << 5, c0 = blockIdx.y << 5;
    const int tx = threadIdx.x, ty = threadIdx.y;  // 32 x 8
    const float nrm = 1.f / (float)(CG * T * HW);

    #pragma unroll
    for (int kk = 0; kk < 4; kk++) {
        int c = c0 + ty + kk * 8;
        int g = c >> 7;
        float sum = g_stats[2 * (b * G + g)];
        float sq  = g_stats[2 * (b * G + g) + 1];
        float mean = sum * nrm;
        float var  = sq * nrm - mean * mean;
        float rstd = rsqrtf(var + EPS);
        float a = rstd * scale[c];
        float d = bias[c] - mean * a;
        float v = x[((size_t)(t * B + b) * C + c) * HW + p0 + tx];
        tile[ty + kk * 8][tx] = v * a + d;
    }
    __syncthreads();
    #pragma unroll
    for (int kk = 0; kk < 4; kk++) {
        int p = p0 + ty + kk * 8;
        float v = tile[tx][ty + kk * 8];
        gb_hnt[(size_t)b * N3 * C + (size_t)(t * HW + p) * C + c0 + tx] = __float2bfloat16(v);
        if (t == 1)
            g_hnt1[(size_t)b * HW * C + (size_t)p * C + c0 + tx] = v;
    }
}

// Convert the three weight matrices to bf16
__global__ void wconv_kernel(const float* __restrict__ kw,
                             const float* __restrict__ vw,
                             const float* __restrict__ pw) {
    int i = blockIdx.x * blockDim.x + threadIdx.x;
    if (i < C * C) {
        gb_kw[i] = __float2bfloat16(kw[i]);
        gb_vw[i] = __float2bfloat16(vw[i]);
        gb_pw[i] = __float2bfloat16(pw[i]);
    }
}

// ---------------------------------------------------------------------------
// BF16 mma.sync GEMM: 128x128 CTA tile, BK=64, 128 threads = 4 warps (2x2),
// warp tile 64x64, m16n8k16. 2-stage cp.async, quad-XOR swizzle.
// C[m,n] = alpha * sum_k A[m,k]*Bm[n,k] (+bias) (+skip^T). K-major operands.
// BIAS_MODE: 0 none, 1 bias[row m], 2 bias[col n].
// OUT_F32: write fp32 to Cf (proj+skip) else bf16 to Cb.
// ---------------------------------------------------------------------------
constexpr int GEMM_SMEM = 2 * 2 * 128 * 128;   // 65536 bytes

template <int BIAS_MODE, bool HAS_SKIP, bool OUT_F32>
__global__ __launch_bounds__(128, 2)
void mma_gemm(const bf16* __restrict__ A, int lda, long long sA,
              const bf16* __restrict__ Bm, int ldb, long long sB,
              float* __restrict__ Cf, bf16* __restrict__ Cb, int ldc, long long sC,
              int K, float alpha, const float* __restrict__ bias,
              const float* __restrict__ skip, int ldsk, long long sSk) {
    extern __shared__ __align__(16) char dsm[];

    const int bz = blockIdx.z;
    A  += (size_t)bz * sA;
    Bm += (size_t)bz * sB;
    if (OUT_F32) Cf += (size_t)bz * sC; else Cb += (size_t)bz * sC;
    if (HAS_SKIP) skip += (size_t)bz * sSk;

    const int bm = blockIdx.x * 128, bn = blockIdx.y * 128;
    const int tid = threadIdx.x, wid = tid >> 5, lane = tid & 31;
    const int wm = wid & 1, wn = wid >> 1;      // warp grid 2 (M) x 2 (N)
    const int gr = lane >> 2, t4 = lane & 3;
    const int grp = lane >> 3, rowin = lane & 7;
    const int qhiA = grp >> 1;                  // A: k-chunk parity per lane group
    const int qhiB = grp & 1;                   // B: k-chunk parity per lane group

    // staging: thread -> row r = tid (one row per thread), 8 16B chunks
    const int r = tid;
    const bf16* Arow = A  + (size_t)(bm + r) * lda;
    const bf16* Brow = Bm + (size_t)(bn + r) * ldb;
    uint32_t off[8];
    #pragma unroll
    for (int j = 0; j < 8; j++)
        off[j] = r * 128 + ((j ^ (r & 7)) << 4);   // bytes within 16KB tile
    const uint32_t smBase = smem_u32(dsm);
    // layout: [buf0 A | buf0 B | buf1 A | buf1 B], 16KB each
    auto stage = [&](int k0, int buf) {
        uint32_t ab = smBase + buf * 32768;
        uint32_t bb = ab + 16384;
        #pragma unroll
        for (int j = 0; j < 8; j++)
            CP_ASYNC16(ab + off[j], Arow + k0 + j * 8);
        #pragma unroll
        for (int j = 0; j < 8; j++)
            CP_ASYNC16(bb + off[j], Brow + k0 + j * 8);
        CP_COMMIT;
    };

    // fragment row byte-offsets
    uint32_t aRow[4], bRow[4];
    #pragma unroll
    for (int mf = 0; mf < 4; mf++)
        aRow[mf] = (uint32_t)(wm * 64 + mf * 16 + (grp & 1) * 8 + rowin) * 128;
    #pragma unroll
    for (int p = 0; p < 4; p++)
        bRow[p] = (uint32_t)(wn * 64 + p * 16 + (grp >> 1) * 8 + rowin) * 128;

    float acc[4][8][4];
    #pragma unroll
    for (int i = 0; i < 4; i++)
        #pragma unroll
        for (int j = 0; j < 8; j++)
            #pragma unroll
            for (int q = 0; q < 4; q++) acc[i][j][q] = 0.f;

    const int nk = K >> 6;                      // BK = 64 bf16
    stage(0, 0);
    for (int kt = 0; kt < nk; kt++) {
        if (kt + 1 < nk) { stage((kt + 1) << 6, (kt + 1) & 1); CP_WAIT1; }
        else             { CP_WAIT0; }
        __syncthreads();
        const uint32_t aB = smBase + (kt & 1) * 32768;
        const uint32_t bB = aB + 16384;
        #pragma unroll
        for (int kk = 0; kk < 4; kk++) {        // 4 x K16 per tile
            uint32_t av[4][4], bv[8][2];
            #pragma unroll
            for (int mf = 0; mf < 4; mf++)
                ldm_x4(av[mf], aB + aRow[mf] + ((((kk << 1) + qhiA) ^ rowin) << 4));
            #pragma unroll
            for (int p = 0; p < 4; p++) {
                uint32_t t[4];
                ldm_x4(t, bB + bRow[p] + ((((kk << 1) + qhiB) ^ rowin) << 4));
                bv[2 * p][0] = t[0]; bv[2 * p][1] = t[1];
                bv[2 * p + 1][0] = t[2]; bv[2 * p + 1][1] = t[3];
            }
            #pragma unroll
            for (int mf = 0; mf < 4; mf++)
                #pragma unroll
                for (int nf = 0; nf < 8; nf++)
                    mma_bf16(acc[mf][nf], av[mf], bv[nf]);
        }
        __syncthreads();
    }

    // epilogue
    #pragma unroll
    for (int mf = 0; mf < 4; mf++) {
        #pragma unroll
        for (int half = 0; half < 2; half++) {
            int rw = bm + wm * 64 + mf * 16 + gr + half * 8;
            float bvv = (BIAS_MODE == 1) ? bias[rw] : 0.f;
            #pragma unroll
            for (int nf = 0; nf < 8; nf++) {
                int cl = bn + wn * 64 + nf * 8 + t4 * 2;
                float ox = acc[mf][nf][half * 2 + 0] * alpha + bvv;
                float oy = acc[mf][nf][half * 2 + 1] * alpha + bvv;
                if (BIAS_MODE == 2) { ox += bias[cl]; oy += bias[cl + 1]; }
                if (HAS_SKIP) {
                    ox += skip[(size_t)cl * ldsk + rw];
                    oy += skip[(size_t)(cl + 1) * ldsk + rw];
                }
                if (OUT_F32) {
                    *reinterpret_cast<float2*>(&Cf[(size_t)rw * ldc + cl]) =
                        make_float2(ox, oy);
                } else {
                    *reinterpret_cast<bf162*>(&Cb[(size_t)rw * ldc + cl]) =
                        __floats2bfloat162_rn(ox, oy);
                }
            }
        }
    }
}

// ---------------------------------------------------------------------------
// FP32 SGEMM (q/skip path). C[m,n] = sum_k A(m,k)*B(n,k) + bias[n].
// Writes fp32 (skip) AND bf16 (scores operand).
// ---------------------------------------------------------------------------
__global__ __launch_bounds__(256, 2)
void sgemm_q(const float* __restrict__ A, int lda, long long sA,
             const float* __restrict__ Bm, int ldb,
             float* __restrict__ Cm, bf16* __restrict__ Cb, int ldc, long long sC,
             int K, const float* __restrict__ bias) {
    const int bz = blockIdx.z;
    A  += (size_t)bz * sA;
    Cm += (size_t)bz * sC;
    Cb += (size_t)bz * sC;

    const int bm = blockIdx.x * 128, bn = blockIdx.y * 128;
    __shared__ float As[2][8][128];
    __shared__ float Bs[2][8][128];
    const int tid = threadIdx.x;
    const int tm  = tid >> 1, tkq = (tid & 1) << 2;

    float acc[8][8];
    #pragma unroll
    for (int i = 0; i < 8; i++)
        #pragma unroll
        for (int j = 0; j < 8; j++) acc[i][j] = 0.f;

    auto ldgA = [&](int k0) -> float4 {
        return *reinterpret_cast<const float4*>(&A[(size_t)(bm + tm) * lda + k0 + tkq]);
    };
    auto ldgB = [&](int k0) -> float4 {
        return *reinterpret_cast<const float4*>(&Bm[(size_t)(bn + tm) * ldb + k0 + tkq]);
    };
    auto stsA = [&](float4 v, int buf) {
        As[buf][tkq + 0][tm] = v.x; As[buf][tkq + 1][tm] = v.y;
        As[buf][tkq + 2][tm] = v.z; As[buf][tkq + 3][tm] = v.w;
    };
    auto stsB = [&](float4 v, int buf) {
        Bs[buf][tkq + 0][tm] = v.x; Bs[buf][tkq + 1][tm] = v.y;
        Bs[buf][tkq + 2][tm] = v.z; Bs[buf][tkq + 3][tm] = v.w;
    };

    float4 pa = ldgA(0), pb = ldgB(0);
    stsA(pa, 0); stsB(pb, 0);
    __syncthreads();

    const int nk = K >> 3;
    const int tx = tid & 15, ty = tid >> 4;
    for (int kt = 0; kt < nk; kt++) {
        const int cur = kt & 1;
        const bool pre = (kt + 1 < nk);
        if (pre) { pa = ldgA((kt + 1) << 3); pb = ldgB((kt + 1) << 3); }
        #pragma unroll
        for (int k = 0; k < 8; k++) {
            float4 a0 = *reinterpret_cast<const float4*>(&As[cur][k][ty << 2]);
            float4 a1 = *reinterpret_cast<const float4*>(&As[cur][k][64 + (ty << 2)]);
            float4 b0 = *reinterpret_cast<const float4*>(&Bs[cur][k][tx << 2]);
            float4 b1 = *reinterpret_cast<const float4*>(&Bs[cur][k][64 + (tx << 2)]);
            float av[8] = {a0.x, a0.y, a0.z, a0.w, a1.x, a1.y, a1.z, a1.w};
            float bv[8] = {b0.x, b0.y, b0.z, b0.w, b1.x, b1.y, b1.z, b1.w};
            #pragma unroll
            for (int i = 0; i < 8; i++)
                #pragma unroll
                for (int j = 0; j < 8; j++)
                    acc[i][j] = fmaf(av[i], bv[j], acc[i][j]);
        }
        if (pre) { stsA(pa, cur ^ 1); stsB(pb, cur ^ 1); }
        __syncthreads();
    }

    #pragma unroll
    for (int i = 0; i < 8; i++) {
        int row = bm + ((i < 4) ? (ty * 4 + i) : (64 + ty * 4 + i - 4));
        #pragma unroll
        for (int jh = 0; jh < 2; jh++) {
            int col = bn + jh * 64 + tx * 4;
            float4 bc = *reinterpret_cast<const float4*>(&bias[col]);
            float4 o;
            o.x = acc[i][jh * 4 + 0] + bc.x;
            o.y = acc[i][jh * 4 + 1] + bc.y;
            o.z = acc[i][jh * 4 + 2] + bc.z;
            o.w = acc[i][jh * 4 + 3] + bc.w;
            *reinterpret_cast<float4*>(&Cm[(size_t)row * ldc + col]) = o;
            bf162* cb = reinterpret_cast<bf162*>(&Cb[(size_t)row * ldc + col]);
            cb[0] = __floats2bfloat162_rn(o.x, o.y);
            cb[1] = __floats2bfloat162_rn(o.z, o.w);
        }
    }
}

// ---------------------------------------------------------------------------
// Row softmax over 6912 bf16 elems; 128 threads/row, fp32 math.
// ---------------------------------------------------------------------------
__global__ void softmax_kernel(bf16* __restrict__ sc) {
    __shared__ float red[4];
    __shared__ float bmax, bsum;
    const int tid = threadIdx.x;
    bf162* row = reinterpret_cast<bf162*>(sc + (size_t)blockIdx.x * N3);

    float2 vals[27];
    float mx = -1e30f;
    #pragma unroll
    for (int i = 0; i < 27; i++) {
        vals[i] = __bfloat1622float2(row[i * 128 + tid]);
        mx = fmaxf(mx, fmaxf(vals[i].x, vals[i].y));
    }
    #pragma unroll
    for (int o = 16; o; o >>= 1) mx = fmaxf(mx, __shfl_xor_sync(0xffffffffu, mx, o));
    if ((tid & 31) == 0) red[tid >> 5] = mx;
    __syncthreads();
    if (tid < 32) {
        float t = (tid < 4) ? red[tid] : -1e30f;
        #pragma unroll
        for (int o = 2; o; o >>= 1) t = fmaxf(t, __shfl_xor_sync(0xffffffffu, t, o));
        if (tid == 0) bmax = t;
    }
    __syncthreads();
    mx = bmax;

    float s = 0.f;
    #pragma unroll
    for (int i = 0; i < 27; i++) {
        vals[i].x = __expf(vals[i].x - mx);
        vals[i].y = __expf(vals[i].y - mx);
        s += vals[i].x + vals[i].y;
    }
    #pragma unroll
    for (int o = 16; o; o >>= 1) s += __shfl_xor_sync(0xffffffffu, s, o);
    if ((tid & 31) == 0) red[tid >> 5] = s;
    __syncthreads();
    if (tid < 32) {
        float t = (tid < 4) ? red[tid] : 0.f;
        #pragma unroll
        for (int o = 2; o; o >>= 1) t += __shfl_xor_sync(0xffffffffu, t, o);
        if (tid == 0) bsum = t;
    }
    __syncthreads();
    float inv = 1.f / bsum;
    #pragma unroll
    for (int i = 0; i < 27; i++)
        row[i * 128 + tid] = __floats2bfloat162_rn(vals[i].x * inv, vals[i].y * inv);
}

// ---------------------------------------------------------------------------
// Launch
// ---------------------------------------------------------------------------
extern "C" void kernel_launch(void* const* d_in, const int* in_sizes, int n_in,
                              void* d_out, int out_size) {
    const float* x   = (const float*)d_in[0];
    const float* nsc = (const float*)d_in[1];
    const float* nbi = (const float*)d_in[2];
    const float* q_w = (const float*)d_in[3];
    const float* q_b = (const float*)d_in[4];
    const float* k_w = (const float*)d_in[5];
    const float* k_b = (const float*)d_in[6];
    const float* v_w = (const float*)d_in[7];
    const float* v_b = (const float*)d_in[8];
    const float* p_w = (const float*)d_in[9];
    const float* p_b = (const float*)d_in[10];
    float* out = (float*)d_out;

    bf16 *hntb, *qtb, *ktb, *vb, *scb, *otb, *kwb, *vwb, *pwb;
    float *hnt1, *qt;
    cudaGetSymbolAddress((void**)&hntb, gb_hnt);
    cudaGetSymbolAddress((void**)&hnt1, g_hnt1);
    cudaGetSymbolAddress((void**)&qt,   g_qt);
    cudaGetSymbolAddress((void**)&qtb,  gb_qt);
    cudaGetSymbolAddress((void**)&ktb,  gb_kt);
    cudaGetSymbolAddress((void**)&vb,   gb_v);
    cudaGetSymbolAddress((void**)&scb,  gb_sc);
    cudaGetSymbolAddress((void**)&otb,  gb_ot);
    cudaGetSymbolAddress((void**)&kwb,  gb_kw);
    cudaGetSymbolAddress((void**)&vwb,  gb_vw);
    cudaGetSymbolAddress((void**)&pwb,  gb_pw);

    cudaFuncSetAttribute(mma_gemm<0, false, false>, cudaFuncAttributeMaxDynamicSharedMemorySize, GEMM_SMEM);
    cudaFuncSetAttribute(mma_gemm<1, false, false>, cudaFuncAttributeMaxDynamicSharedMemorySize, GEMM_SMEM);
    cudaFuncSetAttribute(mma_gemm<2, false, false>, cudaFuncAttributeMaxDynamicSharedMemorySize, GEMM_SMEM);
    cudaFuncSetAttribute(mma_gemm<1, true,  true >, cudaFuncAttributeMaxDynamicSharedMemorySize, GEMM_SMEM);

    const long long sHnt = (long long)N3 * C;
    const long long sH1  = (long long)HW * C;
    const long long sQt  = (long long)HW * C;
    const long long sKt  = (long long)N3 * C;
    const long long sV   = (long long)C * N3;
    const long long sSc  = (long long)HW * N3;
    const long long sOt  = (long long)HW * C;

    // GroupNorm (+ transpose) and weight conversion
    zero_stats_kernel<<<1, 32>>>();
    gn_stats_kernel<<<dim3(B * G, 16), 256>>>(x);
    gn_apply_t_kernel<<<dim3(HW / 32, C / 32, B * T), dim3(32, 8)>>>(x, nsc, nbi);
    wconv_kernel<<<(C * C + 255) / 256, 256>>>(k_w, v_w, p_w);

    // qt[p][o] = hnt1[p][:] . q_w[o][:] + q_b[o]   (fp32 skip + bf16 copy)
    sgemm_q<<<dim3(HW / 128, C / 128, B), 256>>>(
        hnt1, C, sH1, q_w, C, qt, qtb, C, sQt, C, q_b);

    // kt[m][o] = hnt[m][:] . k_w[o][:] + k_b[o]
    mma_gemm<2, false, false><<<dim3(N3 / 128, C / 128, B), 128, GEMM_SMEM>>>(
        hntb, C, sHnt, kwb, C, 0, nullptr, ktb, C, sKt, C, 1.f, k_b, nullptr, 0, 0);

    // v[c][m] = v_w[c][:] . hnt[m][:] + v_b[c]
    mma_gemm<1, false, false><<<dim3(C / 128, N3 / 128, B), 128, GEMM_SMEM>>>(
        vwb, C, 0, hntb, C, sHnt, nullptr, vb, N3, sV, C, 1.f, v_b, nullptr, 0, 0);

    // scores[p][m] = (qt[p][:] . kt[m][:]) * C^-0.5
    mma_gemm<0, false, false><<<dim3(HW / 128, N3 / 128, B), 128, GEMM_SMEM>>>(
        qtb, C, sQt, ktb, C, sKt, nullptr, scb, N3, sSc, C,
        0.044194173824159216f, nullptr, nullptr, 0, 0);

    softmax_kernel<<<B * HW, 128>>>(scb);

    // ot[p][c] = attn[p][:] . v[c][:]
    mma_gemm<0, false, false><<<dim3(HW / 128, C / 128, B), 128, GEMM_SMEM>>>(
        scb, N3, sSc, vb, N3, sV, nullptr, otb, C, sOt, N3, 1.f,
        nullptr, nullptr, 0, 0);

    // out[o][p] = p_w[o][:] . ot[p][:] + p_b[o] + qt[p][o]   (fp32 out)
    mma_gemm<1, true, true><<<dim3(C / 128, HW / 128, B), 128, GEMM_SMEM>>>(
        pwb, C, 0, otb, C, sOt, out, nullptr, HW, (long long)C * HW, C, 1.f, p_b,
        qt, C, sQt);
}

// round 10
// speedup vs baseline: 1.2829x; 1.2829x over previous
#include <cuda_runtime.h>
#include <cuda_bf16.h>
#include <cstdint>

constexpr int B  = 4;
constexpr int C  = 512;
constexpr int T  = 3;
constexpr int HW = 2304;   // 48*48
constexpr int N3 = 6912;   // 3*HW
constexpr int G  = 4;
constexpr int CG = C / G;  // 128
constexpr int KQ = 3 * C;  // 1536: split-bf16 concat K for q
constexpr float EPS = 1e-6f;

typedef __nv_bfloat16  bf16;
typedef __nv_bfloat162 bf162;

// Scratch
__device__ bf16  gb_hnt[(size_t)B * N3 * C];   // normalized, transposed, bf16
__device__ bf16  gb_hq [(size_t)B * HW * KQ];  // t=1 slice split [hi|lo|hi]
__device__ float g_qt  [(size_t)B * HW * C];   // q fp32 (skip)
__device__ bf16  gb_qt [(size_t)B * HW * C];   // q bf16 (scores operand)
__device__ bf16  gb_kt [(size_t)B * N3 * C];   // k [m][c]
__device__ bf16  gb_v  [(size_t)B * C * N3];   // v [c][m]
__device__ bf16  gb_sc [(size_t)B * HW * N3];  // scores / attn [p][m]
__device__ bf16  gb_ot [(size_t)B * HW * C];   // attn out [p][c]
__device__ bf16  gb_kw[C * C], gb_vw[C * C], gb_pw[C * C];
__device__ bf16  gb_qw[C * KQ];                // q weights split [hi|hi|lo]
__device__ float g_stats[2 * B * G];

__device__ __forceinline__ uint32_t smem_u32(const void* p) {
    return (uint32_t)__cvta_generic_to_shared(p);
}
#define CP_ASYNC16(sm, gm) \
    asm volatile("cp.async.ca.shared.global [%0], [%1], 16;" :: "r"(sm), "l"(gm))
#define CP_COMMIT asm volatile("cp.async.commit_group;")
#define CP_WAIT1  asm volatile("cp.async.wait_group 1;")
#define CP_WAIT0  asm volatile("cp.async.wait_group 0;")

__device__ __forceinline__ void ldm_x4(uint32_t* r, uint32_t addr) {
    asm volatile("ldmatrix.sync.aligned.m8n8.x4.shared.b16 {%0,%1,%2,%3}, [%4];"
        : "=r"(r[0]), "=r"(r[1]), "=r"(r[2]), "=r"(r[3]) : "r"(addr));
}
__device__ __forceinline__ void mma_bf16(float* c, const uint32_t* a, const uint32_t* b) {
    asm volatile("mma.sync.aligned.m16n8k16.row.col.f32.bf16.bf16.f32 "
        "{%0,%1,%2,%3}, {%4,%5,%6,%7}, {%8,%9}, {%0,%1,%2,%3};"
        : "+f"(c[0]), "+f"(c[1]), "+f"(c[2]), "+f"(c[3])
        : "r"(a[0]), "r"(a[1]), "r"(a[2]), "r"(a[3]), "r"(b[0]), "r"(b[1]));
}

// ---------------------------------------------------------------------------
// GroupNorm
// ---------------------------------------------------------------------------
__global__ void zero_stats_kernel() {
    if (threadIdx.x < 2 * B * G) g_stats[threadIdx.x] = 0.f;
}

__global__ void gn_stats_kernel(const float* __restrict__ x) {
    const int bg = blockIdx.x;
    const int b = bg >> 2, g = bg & 3;
    const int TOT4 = CG * T * HW / 4;
    const int PER  = TOT4 / 16;
    const int start = blockIdx.y * PER;

    float s = 0.f, ss = 0.f;
    for (int i = start + threadIdx.x; i < start + PER; i += blockDim.x) {
        int cl = i / (T * HW / 4);
        int r  = i - cl * (T * HW / 4);
        int t  = r / (HW / 4);
        int p4 = r - t * (HW / 4);
        float4 v = reinterpret_cast<const float4*>(x)[
            ((size_t)(t * B + b) * C + g * CG + cl) * (HW / 4) + p4];
        s  += v.x + v.y + v.z + v.w;
        ss += v.x * v.x + v.y * v.y + v.z * v.z + v.w * v.w;
    }
    __shared__ float rs[8], rss[8];
    #pragma unroll
    for (int o = 16; o; o >>= 1) {
        s  += __shfl_xor_sync(0xffffffffu, s, o);
        ss += __shfl_xor_sync(0xffffffffu, ss, o);
    }
    if ((threadIdx.x & 31) == 0) { rs[threadIdx.x >> 5] = s; rss[threadIdx.x >> 5] = ss; }
    __syncthreads();
    if (threadIdx.x == 0) {
        float a = 0.f, c = 0.f;
        #pragma unroll
        for (int i = 0; i < 8; i++) { a += rs[i]; c += rss[i]; }
        atomicAdd(&g_stats[2 * bg],     a);
        atomicAdd(&g_stats[2 * bg + 1], c);
    }
}

// normalize + affine + transpose -> gb_hnt (bf16); t=1 slice split hi/lo
__global__ void gn_apply_t_kernel(const float* __restrict__ x,
                                  const float* __restrict__ scale,
                                  const float* __restrict__ bias) {
    __shared__ float tile[32][33];
    const int bt = blockIdx.z;
    const int b = bt / T, t = bt - b * T;
    const int p0 = blockIdx.x << 5, c0 = blockIdx.y << 5;
    const int tx = threadIdx.x, ty = threadIdx.y;  // 32 x 8
    const float nrm = 1.f / (float)(CG * T * HW);

    #pragma unroll
    for (int kk = 0; kk < 4; kk++) {
        int c = c0 + ty + kk * 8;
        int g = c >> 7;
        float sum = g_stats[2 * (b * G + g)];
        float sq  = g_stats[2 * (b * G + g) + 1];
        float mean = sum * nrm;
        float var  = sq * nrm - mean * mean;
        float rstd = rsqrtf(var + EPS);
        float a = rstd * scale[c];
        float d = bias[c] - mean * a;
        float v = x[((size_t)(t * B + b) * C + c) * HW + p0 + tx];
        tile[ty + kk * 8][tx] = v * a + d;
    }
    __syncthreads();
    #pragma unroll
    for (int kk = 0; kk < 4; kk++) {
        int p = p0 + ty + kk * 8;
        float v = tile[tx][ty + kk * 8];
        bf16 hi = __float2bfloat16(v);
        gb_hnt[(size_t)b * N3 * C + (size_t)(t * HW + p) * C + c0 + tx] = hi;
        if (t == 1) {
            bf16 lo = __float2bfloat16(v - __bfloat162float(hi));
            size_t base = ((size_t)b * HW + p) * KQ + c0 + tx;
            gb_hq[base]            = hi;
            gb_hq[base + C]        = lo;
            gb_hq[base + 2 * C]    = hi;
        }
    }
}

// Convert weights: k/v/p to bf16; q to split [hi|hi|lo] layout
__global__ void wconv_kernel(const float* __restrict__ kw,
                             const float* __restrict__ vw,
                             const float* __restrict__ pw,
                             const float* __restrict__ qw) {
    int i = blockIdx.x * blockDim.x + threadIdx.x;
    if (i < C * C) {
        gb_kw[i] = __float2bfloat16(kw[i]);
        gb_vw[i] = __float2bfloat16(vw[i]);
        gb_pw[i] = __float2bfloat16(pw[i]);
        float w = qw[i];
        bf16 hi = __float2bfloat16(w);
        bf16 lo = __float2bfloat16(w - __bfloat162float(hi));
        int o = i / C, c = i - o * C;
        gb_qw[(size_t)o * KQ + c]         = hi;
        gb_qw[(size_t)o * KQ + C + c]     = hi;
        gb_qw[(size_t)o * KQ + 2 * C + c] = lo;
    }
}

// ---------------------------------------------------------------------------
// BF16 mma.sync GEMM: 128x128 tile, BK=64, 8 warps (2x4), warp 64x32,
// m16n8k16, 2-stage cp.async, quad-XOR swizzle (tile = 128 rows x 128B).
// C[m,n] = alpha * sum_k A[m,k]*Bm[n,k] (+bias) (+skip^T). K-major operands.
// BIAS_MODE: 0 none, 1 bias[row m], 2 bias[col n].
// OUT: 0 = bf16 -> Cb, 1 = fp32 -> Cf, 2 = both.
// ---------------------------------------------------------------------------
constexpr int GEMM_SMEM = 2 * 2 * 128 * 128;   // 65536 bytes

template <int BIAS_MODE, bool HAS_SKIP, int OUT>
__global__ __launch_bounds__(256, 2)
void mma_gemm(const bf16* __restrict__ A, int lda, long long sA,
              const bf16* __restrict__ Bm, int ldb, long long sB,
              float* __restrict__ Cf, bf16* __restrict__ Cb, int ldc, long long sC,
              int K, float alpha, const float* __restrict__ bias,
              const float* __restrict__ skip, int ldsk, long long sSk) {
    extern __shared__ __align__(16) char dsm[];

    const int bz = blockIdx.z;
    A  += (size_t)bz * sA;
    Bm += (size_t)bz * sB;
    if (OUT != 0) Cf += (size_t)bz * sC;
    if (OUT != 1) Cb += (size_t)bz * sC;
    if (HAS_SKIP) skip += (size_t)bz * sSk;

    const int bm = blockIdx.x * 128, bn = blockIdx.y * 128;
    const int tid = threadIdx.x, wid = tid >> 5, lane = tid & 31;
    const int wm = wid & 1, wn = wid >> 1;      // warp grid 2 (M) x 4 (N)
    const int gr = lane >> 2, t4 = lane & 3;
    const int grp = lane >> 3, rowin = lane & 7;
    const int qhiA = grp >> 1;                  // A: k-chunk parity per lane group
    const int qhiB = grp & 1;                   // B: k-chunk parity per lane group

    // staging: thread -> row r = tid>>1, 16B chunks q0..q0+3 of that row
    const int r  = tid >> 1;
    const int q0 = (tid & 1) * 4;
    const bf16* Arow = A  + (size_t)(bm + r) * lda;
    const bf16* Brow = Bm + (size_t)(bn + r) * ldb;
    uint32_t off[4];
    #pragma unroll
    for (int j = 0; j < 4; j++)
        off[j] = r * 128 + (((q0 + j) ^ (r & 7)) << 4);   // bytes within 16KB tile
    const uint32_t smBase = smem_u32(dsm);
    // layout: [buf0 A | buf0 B | buf1 A | buf1 B], 16KB each
    auto stage = [&](int k0, int buf) {
        uint32_t ab = smBase + buf * 32768;
        uint32_t bb = ab + 16384;
        #pragma unroll
        for (int j = 0; j < 4; j++) {
            CP_ASYNC16(ab + off[j], Arow + k0 + (q0 + j) * 8);
            CP_ASYNC16(bb + off[j], Brow + k0 + (q0 + j) * 8);
        }
        CP_COMMIT;
    };

    // fragment row byte-offsets
    uint32_t aRow[4], bRow[2];
    #pragma unroll
    for (int mf = 0; mf < 4; mf++)
        aRow[mf] = (uint32_t)(wm * 64 + mf * 16 + (grp & 1) * 8 + rowin) * 128;
    #pragma unroll
    for (int p = 0; p < 2; p++)
        bRow[p] = (uint32_t)(wn * 32 + p * 16 + (grp >> 1) * 8 + rowin) * 128;

    float acc[4][4][4];
    #pragma unroll
    for (int i = 0; i < 4; i++)
        #pragma unroll
        for (int j = 0; j < 4; j++)
            #pragma unroll
            for (int q = 0; q < 4; q++) acc[i][j][q] = 0.f;

    const int nk = K >> 6;                      // BK = 64 bf16
    stage(0, 0);
    for (int kt = 0; kt < nk; kt++) {
        if (kt + 1 < nk) { stage((kt + 1) << 6, (kt + 1) & 1); CP_WAIT1; }
        else             { CP_WAIT0; }
        __syncthreads();
        const uint32_t aB = smBase + (kt & 1) * 32768;
        const uint32_t bB = aB + 16384;
        #pragma unroll
        for (int kk = 0; kk < 4; kk++) {        // 4 x K16 per tile
            uint32_t av[4][4], bv[4][2];
            #pragma unroll
            for (int mf = 0; mf < 4; mf++)
                ldm_x4(av[mf], aB + aRow[mf] + ((((kk << 1) + qhiA) ^ rowin) << 4));
            #pragma unroll
            for (int p = 0; p < 2; p++) {
                uint32_t t[4];
                ldm_x4(t, bB + bRow[p] + ((((kk << 1) + qhiB) ^ rowin) << 4));
                bv[2 * p][0] = t[0]; bv[2 * p][1] = t[1];
                bv[2 * p + 1][0] = t[2]; bv[2 * p + 1][1] = t[3];
            }
            #pragma unroll
            for (int mf = 0; mf < 4; mf++)
                #pragma unroll
                for (int nf = 0; nf < 4; nf++)
                    mma_bf16(acc[mf][nf], av[mf], bv[nf]);
        }
        __syncthreads();
    }

    // epilogue
    #pragma unroll
    for (int mf = 0; mf < 4; mf++) {
        #pragma unroll
        for (int half = 0; half < 2; half++) {
            int rw = bm + wm * 64 + mf * 16 + gr + half * 8;
            float bvv = (BIAS_MODE == 1) ? bias[rw] : 0.f;
            #pragma unroll
            for (int nf = 0; nf < 4; nf++) {
                int cl = bn + wn * 32 + nf * 8 + t4 * 2;
                float ox = acc[mf][nf][half * 2 + 0] * alpha + bvv;
                float oy = acc[mf][nf][half * 2 + 1] * alpha + bvv;
                if (BIAS_MODE == 2) { ox += bias[cl]; oy += bias[cl + 1]; }
                if (HAS_SKIP) {
                    ox += skip[(size_t)cl * ldsk + rw];
                    oy += skip[(size_t)(cl + 1) * ldsk + rw];
                }
                if (OUT != 0)
                    *reinterpret_cast<float2*>(&Cf[(size_t)rw * ldc + cl]) =
                        make_float2(ox, oy);
                if (OUT != 1)
                    *reinterpret_cast<bf162*>(&Cb[(size_t)rw * ldc + cl]) =
                        __floats2bfloat162_rn(ox, oy);
            }
        }
    }
}

// ---------------------------------------------------------------------------
// Row softmax over 6912 bf16 elems; 128 threads/row, fp32 math.
// ---------------------------------------------------------------------------
__global__ void softmax_kernel(bf16* __restrict__ sc) {
    __shared__ float red[4];
    __shared__ float bmax, bsum;
    const int tid = threadIdx.x;
    bf162* row = reinterpret_cast<bf162*>(sc + (size_t)blockIdx.x * N3);

    float2 vals[27];
    float mx = -1e30f;
    #pragma unroll
    for (int i = 0; i < 27; i++) {
        vals[i] = __bfloat1622float2(row[i * 128 + tid]);
        mx = fmaxf(mx, fmaxf(vals[i].x, vals[i].y));
    }
    #pragma unroll
    for (int o = 16; o; o >>= 1) mx = fmaxf(mx, __shfl_xor_sync(0xffffffffu, mx, o));
    if ((tid & 31) == 0) red[tid >> 5] = mx;
    __syncthreads();
    if (tid < 32) {
        float t = (tid < 4) ? red[tid] : -1e30f;
        #pragma unroll
        for (int o = 2; o; o >>= 1) t = fmaxf(t, __shfl_xor_sync(0xffffffffu, t, o));
        if (tid == 0) bmax = t;
    }
    __syncthreads();
    mx = bmax;

    float s = 0.f;
    #pragma unroll
    for (int i = 0; i < 27; i++) {
        vals[i].x = __expf(vals[i].x - mx);
        vals[i].y = __expf(vals[i].y - mx);
        s += vals[i].x + vals[i].y;
    }
    #pragma unroll
    for (int o = 16; o; o >>= 1) s += __shfl_xor_sync(0xffffffffu, s, o);
    if ((tid & 31) == 0) red[tid >> 5] = s;
    __syncthreads();
    if (tid < 32) {
        float t = (tid < 4) ? red[tid] : 0.f;
        #pragma unroll
        for (int o = 2; o; o >>= 1) t += __shfl_xor_sync(0xffffffffu, t, o);
        if (tid == 0) bsum = t;
    }
    __syncthreads();
    float inv = 1.f / bsum;
    #pragma unroll
    for (int i = 0; i < 27; i++)
        row[i * 128 + tid] = __floats2bfloat162_rn(vals[i].x * inv, vals[i].y * inv);
}

// ---------------------------------------------------------------------------
// Launch
// ---------------------------------------------------------------------------
extern "C" void kernel_launch(void* const* d_in, const int* in_sizes, int n_in,
                              void* d_out, int out_size) {
    const float* x   = (const float*)d_in[0];
    const float* nsc = (const float*)d_in[1];
    const float* nbi = (const float*)d_in[2];
    const float* q_w = (const float*)d_in[3];
    const float* q_b = (const float*)d_in[4];
    const float* k_w = (const float*)d_in[5];
    const float* k_b = (const float*)d_in[6];
    const float* v_w = (const float*)d_in[7];
    const float* v_b = (const float*)d_in[8];
    const float* p_w = (const float*)d_in[9];
    const float* p_b = (const float*)d_in[10];
    float* out = (float*)d_out;

    bf16 *hntb, *hqb, *qtb, *ktb, *vb, *scb, *otb, *kwb, *vwb, *pwb, *qwb;
    float *qt;
    cudaGetSymbolAddress((void**)&hntb, gb_hnt);
    cudaGetSymbolAddress((void**)&hqb,  gb_hq);
    cudaGetSymbolAddress((void**)&qt,   g_qt);
    cudaGetSymbolAddress((void**)&qtb,  gb_qt);
    cudaGetSymbolAddress((void**)&ktb,  gb_kt);
    cudaGetSymbolAddress((void**)&vb,   gb_v);
    cudaGetSymbolAddress((void**)&scb,  gb_sc);
    cudaGetSymbolAddress((void**)&otb,  gb_ot);
    cudaGetSymbolAddress((void**)&kwb,  gb_kw);
    cudaGetSymbolAddress((void**)&vwb,  gb_vw);
    cudaGetSymbolAddress((void**)&pwb,  gb_pw);
    cudaGetSymbolAddress((void**)&qwb,  gb_qw);

    cudaFuncSetAttribute(mma_gemm<0, false, 0>, cudaFuncAttributeMaxDynamicSharedMemorySize, GEMM_SMEM);
    cudaFuncSetAttribute(mma_gemm<1, false, 0>, cudaFuncAttributeMaxDynamicSharedMemorySize, GEMM_SMEM);
    cudaFuncSetAttribute(mma_gemm<2, false, 0>, cudaFuncAttributeMaxDynamicSharedMemorySize, GEMM_SMEM);
    cudaFuncSetAttribute(mma_gemm<2, false, 2>, cudaFuncAttributeMaxDynamicSharedMemorySize, GEMM_SMEM);
    cudaFuncSetAttribute(mma_gemm<1, true,  1>, cudaFuncAttributeMaxDynamicSharedMemorySize, GEMM_SMEM);

    const long long sHnt = (long long)N3 * C;
    const long long sHq  = (long long)HW * KQ;
    const long long sQt  = (long long)HW * C;
    const long long sKt  = (long long)N3 * C;
    const long long sV   = (long long)C * N3;
    const long long sSc  = (long long)HW * N3;
    const long long sOt  = (long long)HW * C;

    // GroupNorm (+ transpose) and weight conversion
    zero_stats_kernel<<<1, 32>>>();
    gn_stats_kernel<<<dim3(B * G, 16), 256>>>(x);
    gn_apply_t_kernel<<<dim3(HW / 32, C / 32, B * T), dim3(32, 8)>>>(x, nsc, nbi);
    wconv_kernel<<<(C * C + 255) / 256, 256>>>(k_w, v_w, p_w, q_w);

    // q (split-bf16 compensated, K=1536): qt[p][o] fp32 + bf16, + q_b[o]
    mma_gemm<2, false, 2><<<dim3(HW / 128, C / 128, B), 256, GEMM_SMEM>>>(
        hqb, KQ, sHq, qwb, KQ, 0, qt, qtb, C, sQt, KQ, 1.f, q_b, nullptr, 0, 0);

    // kt[m][o] = hnt[m][:] . k_w[o][:] + k_b[o]
    mma_gemm<2, false, 0><<<dim3(N3 / 128, C / 128, B), 256, GEMM_SMEM>>>(
        hntb, C, sHnt, kwb, C, 0, nullptr, ktb, C, sKt, C, 1.f, k_b, nullptr, 0, 0);

    // v[c][m] = v_w[c][:] . hnt[m][:] + v_b[c]
    mma_gemm<1, false, 0><<<dim3(C / 128, N3 / 128, B), 256, GEMM_SMEM>>>(
        vwb, C, 0, hntb, C, sHnt, nullptr, vb, N3, sV, C, 1.f, v_b, nullptr, 0, 0);

    // scores[p][m] = (qt[p][:] . kt[m][:]) * C^-0.5
    mma_gemm<0, false, 0><<<dim3(HW / 128, N3 / 128, B), 256, GEMM_SMEM>>>(
        qtb, C, sQt, ktb, C, sKt, nullptr, scb, N3, sSc, C,
        0.044194173824159216f, nullptr, nullptr, 0, 0);

    softmax_kernel<<<B * HW, 128>>>(scb);

    // ot[p][c] = attn[p][:] . v[c][:]
    mma_gemm<0, false, 0><<<dim3(HW / 128, C / 128, B), 256, GEMM_SMEM>>>(
        scb, N3, sSc, vb, N3, sV, nullptr, otb, C, sOt, N3, 1.f,
        nullptr, nullptr, 0, 0);

    // out[o][p] = p_w[o][:] . ot[p][:] + p_b[o] + qt[p][o]   (fp32 out)
    mma_gemm<1, true, 1><<<dim3(C / 128, HW / 128, B), 256, GEMM_SMEM>>>(
        pwb, C, 0, otb, C, sOt, out, nullptr, HW, (long long)C * HW, C, 1.f, p_b,
        qt, C, sQt);
}

// round 11
// speedup vs baseline: 1.3817x; 1.0770x over previous
#include <cuda_runtime.h>
#include <cuda_bf16.h>
#include <cstdint>

constexpr int B  = 4;
constexpr int C  = 512;
constexpr int T  = 3;
constexpr int HW = 2304;   // 48*48
constexpr int N3 = 6912;   // 3*HW
constexpr int G  = 4;
constexpr int CG = C / G;  // 128
constexpr int KQ = 3 * C;  // 1536: split-bf16 concat K for q
constexpr float EPS = 1e-6f;

typedef __nv_bfloat16  bf16;
typedef __nv_bfloat162 bf162;

// Scratch
__device__ bf16  gb_hnt[(size_t)B * N3 * C];   // normalized, transposed, bf16
__device__ bf16  gb_hq [(size_t)B * HW * KQ];  // t=1 slice split [hi|lo|hi]
__device__ float g_qt  [(size_t)B * HW * C];   // q fp32 (skip)
__device__ bf16  gb_qt [(size_t)B * HW * C];   // q bf16 (scores operand)
__device__ bf16  gb_kt [(size_t)B * N3 * C];   // k [m][c]
__device__ bf16  gb_v  [(size_t)B * C * N3];   // v [c][m]
__device__ bf16  gb_sc [(size_t)B * HW * N3];  // exp(scores) [p][m]
__device__ bf16  gb_ot [(size_t)B * HW * C];   // attn out [p][c]
__device__ bf16  gb_kw[C * C], gb_vw[C * C], gb_pw[C * C];
__device__ bf16  gb_qw[C * KQ];                // q weights split [hi|hi|lo]
__device__ float g_stats[2 * B * G];
__device__ float g_Z[(size_t)B * HW];          // softmax denominators

__device__ __forceinline__ uint32_t smem_u32(const void* p) {
    return (uint32_t)__cvta_generic_to_shared(p);
}
#define CP_ASYNC16(sm, gm) \
    asm volatile("cp.async.cg.shared.global [%0], [%1], 16;" :: "r"(sm), "l"(gm))
#define CP_COMMIT asm volatile("cp.async.commit_group;")
#define CP_WAIT1  asm volatile("cp.async.wait_group 1;")
#define CP_WAIT0  asm volatile("cp.async.wait_group 0;")

__device__ __forceinline__ void ldm_x4(uint32_t* r, uint32_t addr) {
    asm volatile("ldmatrix.sync.aligned.m8n8.x4.shared.b16 {%0,%1,%2,%3}, [%4];"
        : "=r"(r[0]), "=r"(r[1]), "=r"(r[2]), "=r"(r[3]) : "r"(addr));
}
__device__ __forceinline__ void mma_bf16(float* c, const uint32_t* a, const uint32_t* b) {
    asm volatile("mma.sync.aligned.m16n8k16.row.col.f32.bf16.bf16.f32 "
        "{%0,%1,%2,%3}, {%4,%5,%6,%7}, {%8,%9}, {%0,%1,%2,%3};"
        : "+f"(c[0]), "+f"(c[1]), "+f"(c[2]), "+f"(c[3])
        : "r"(a[0]), "r"(a[1]), "r"(a[2]), "r"(a[3]), "r"(b[0]), "r"(b[1]));
}

// ---------------------------------------------------------------------------
// Zero stats + Z
// ---------------------------------------------------------------------------
__global__ void zero_kernel() {
    int i = blockIdx.x * blockDim.x + threadIdx.x;
    if (i < B * HW) g_Z[i] = 0.f;
    if (i < 2 * B * G) g_stats[i] = 0.f;
}

__global__ void gn_stats_kernel(const float* __restrict__ x) {
    const int bg = blockIdx.x;
    const int b = bg >> 2, g = bg & 3;
    const int TOT4 = CG * T * HW / 4;
    const int PER  = TOT4 / 16;
    const int start = blockIdx.y * PER;

    float s = 0.f, ss = 0.f;
    for (int i = start + threadIdx.x; i < start + PER; i += blockDim.x) {
        int cl = i / (T * HW / 4);
        int r  = i - cl * (T * HW / 4);
        int t  = r / (HW / 4);
        int p4 = r - t * (HW / 4);
        float4 v = reinterpret_cast<const float4*>(x)[
            ((size_t)(t * B + b) * C + g * CG + cl) * (HW / 4) + p4];
        s  += v.x + v.y + v.z + v.w;
        ss += v.x * v.x + v.y * v.y + v.z * v.z + v.w * v.w;
    }
    __shared__ float rs[8], rss[8];
    #pragma unroll
    for (int o = 16; o; o >>= 1) {
        s  += __shfl_xor_sync(0xffffffffu, s, o);
        ss += __shfl_xor_sync(0xffffffffu, ss, o);
    }
    if ((threadIdx.x & 31) == 0) { rs[threadIdx.x >> 5] = s; rss[threadIdx.x >> 5] = ss; }
    __syncthreads();
    if (threadIdx.x == 0) {
        float a = 0.f, c = 0.f;
        #pragma unroll
        for (int i = 0; i < 8; i++) { a += rs[i]; c += rss[i]; }
        atomicAdd(&g_stats[2 * bg],     a);
        atomicAdd(&g_stats[2 * bg + 1], c);
    }
}

// normalize + affine + transpose -> gb_hnt (bf16); t=1 slice split hi/lo
__global__ void gn_apply_t_kernel(const float* __restrict__ x,
                                  const float* __restrict__ scale,
                                  const float* __restrict__ bias) {
    __shared__ float tile[32][33];
    const int bt = blockIdx.z;
    const int b = bt / T, t = bt - b * T;
    const int p0 = blockIdx.x << 5, c0 = blockIdx.y << 5;
    const int tx = threadIdx.x, ty = threadIdx.y;  // 32 x 8
    const float nrm = 1.f / (float)(CG * T * HW);

    #pragma unroll
    for (int kk = 0; kk < 4; kk++) {
        int c = c0 + ty + kk * 8;
        int g = c >> 7;
        float sum = g_stats[2 * (b * G + g)];
        float sq  = g_stats[2 * (b * G + g) + 1];
        float mean = sum * nrm;
        float var  = sq * nrm - mean * mean;
        float rstd = rsqrtf(var + EPS);
        float a = rstd * scale[c];
        float d = bias[c] - mean * a;
        float v = x[((size_t)(t * B + b) * C + c) * HW + p0 + tx];
        tile[ty + kk * 8][tx] = v * a + d;
    }
    __syncthreads();
    #pragma unroll
    for (int kk = 0; kk < 4; kk++) {
        int p = p0 + ty + kk * 8;
        float v = tile[tx][ty + kk * 8];
        bf16 hi = __float2bfloat16(v);
        gb_hnt[(size_t)b * N3 * C + (size_t)(t * HW + p) * C + c0 + tx] = hi;
        if (t == 1) {
            bf16 lo = __float2bfloat16(v - __bfloat162float(hi));
            size_t base = ((size_t)b * HW + p) * KQ + c0 + tx;
            gb_hq[base]            = hi;
            gb_hq[base + C]        = lo;
            gb_hq[base + 2 * C]    = hi;
        }
    }
}

// Convert weights: k/v/p to bf16; q to split [hi|hi|lo] layout
__global__ void wconv_kernel(const float* __restrict__ kw,
                             const float* __restrict__ vw,
                             const float* __restrict__ pw,
                             const float* __restrict__ qw) {
    int i = blockIdx.x * blockDim.x + threadIdx.x;
    if (i < C * C) {
        gb_kw[i] = __float2bfloat16(kw[i]);
        gb_vw[i] = __float2bfloat16(vw[i]);
        gb_pw[i] = __float2bfloat16(pw[i]);
        float w = qw[i];
        bf16 hi = __float2bfloat16(w);
        bf16 lo = __float2bfloat16(w - __bfloat162float(hi));
        int o = i / C, c = i - o * C;
        gb_qw[(size_t)o * KQ + c]         = hi;
        gb_qw[(size_t)o * KQ + C + c]     = hi;
        gb_qw[(size_t)o * KQ + 2 * C + c] = lo;
    }
}

// ---------------------------------------------------------------------------
// BF16 mma.sync GEMM: 128x128 tile, BK=64, 8 warps (2x4), warp 64x32,
// m16n8k16, 2-stage cp.async, quad-XOR swizzle.
// C[m,n] = alpha * sum_k A[m,k]*Bm[n,k] (+bias) (+skip^T). K-major operands.
// BIAS_MODE: 0 none, 1 bias[row m], 2 bias[col n].
// OUT: 0 = bf16 -> Cb, 1 = fp32 -> Cf, 2 = both.
// SM_MODE: 0 none, 1 = exp + row-sum atomics into Z (scores),
//          2 = scale output rows by 1/Z[row] (attn*V).
// ---------------------------------------------------------------------------
constexpr int GEMM_SMEM = 2 * 2 * 128 * 128;   // 65536 bytes

template <int BIAS_MODE, bool HAS_SKIP, int OUT, int SM_MODE>
__global__ __launch_bounds__(256, 2)
void mma_gemm(const bf16* __restrict__ A, int lda, long long sA,
              const bf16* __restrict__ Bm, int ldb, long long sB,
              float* __restrict__ Cf, bf16* __restrict__ Cb, int ldc, long long sC,
              int K, float alpha, const float* __restrict__ bias,
              const float* __restrict__ skip, int ldsk, long long sSk,
              float* __restrict__ Z) {
    extern __shared__ __align__(16) char dsm[];

    const int bz = blockIdx.z;
    A  += (size_t)bz * sA;
    Bm += (size_t)bz * sB;
    if (OUT != 0) Cf += (size_t)bz * sC;
    if (OUT != 1) Cb += (size_t)bz * sC;
    if (HAS_SKIP) skip += (size_t)bz * sSk;
    if (SM_MODE != 0) Z += (size_t)bz * HW;

    const int bm = blockIdx.x * 128, bn = blockIdx.y * 128;
    const int tid = threadIdx.x, wid = tid >> 5, lane = tid & 31;
    const int wm = wid & 1, wn = wid >> 1;      // warp grid 2 (M) x 4 (N)
    const int gr = lane >> 2, t4 = lane & 3;
    const int grp = lane >> 3, rowin = lane & 7;
    const int qhiA = grp >> 1;
    const int qhiB = grp & 1;

    // staging: thread -> row r = tid>>1, 16B chunks q0..q0+3 of that row
    const int r  = tid >> 1;
    const int q0 = (tid & 1) * 4;
    const bf16* Arow = A  + (size_t)(bm + r) * lda;
    const bf16* Brow = Bm + (size_t)(bn + r) * ldb;
    uint32_t off[4];
    #pragma unroll
    for (int j = 0; j < 4; j++)
        off[j] = r * 128 + (((q0 + j) ^ (r & 7)) << 4);   // bytes within 16KB tile
    const uint32_t smBase = smem_u32(dsm);
    // layout: [buf0 A | buf0 B | buf1 A | buf1 B], 16KB each
    auto stage = [&](int k0, int buf) {
        uint32_t ab = smBase + buf * 32768;
        uint32_t bb = ab + 16384;
        #pragma unroll
        for (int j = 0; j < 4; j++) {
            CP_ASYNC16(ab + off[j], Arow + k0 + (q0 + j) * 8);
            CP_ASYNC16(bb + off[j], Brow + k0 + (q0 + j) * 8);
        }
        CP_COMMIT;
    };

    // fragment row byte-offsets
    uint32_t aRow[4], bRow[2];
    #pragma unroll
    for (int mf = 0; mf < 4; mf++)
        aRow[mf] = (uint32_t)(wm * 64 + mf * 16 + (grp & 1) * 8 + rowin) * 128;
    #pragma unroll
    for (int p = 0; p < 2; p++)
        bRow[p] = (uint32_t)(wn * 32 + p * 16 + (grp >> 1) * 8 + rowin) * 128;

    float acc[4][4][4];
    #pragma unroll
    for (int i = 0; i < 4; i++)
        #pragma unroll
        for (int j = 0; j < 4; j++)
            #pragma unroll
            for (int q = 0; q < 4; q++) acc[i][j][q] = 0.f;

    const int nk = K >> 6;                      // BK = 64 bf16
    stage(0, 0);
    for (int kt = 0; kt < nk; kt++) {
        if (kt + 1 < nk) { stage((kt + 1) << 6, (kt + 1) & 1); CP_WAIT1; }
        else             { CP_WAIT0; }
        __syncthreads();
        const uint32_t aB = smBase + (kt & 1) * 32768;
        const uint32_t bB = aB + 16384;
        #pragma unroll
        for (int kk = 0; kk < 4; kk++) {        // 4 x K16 per tile
            uint32_t av[4][4], bv[4][2];
            #pragma unroll
            for (int mf = 0; mf < 4; mf++)
                ldm_x4(av[mf], aB + aRow[mf] + ((((kk << 1) + qhiA) ^ rowin) << 4));
            #pragma unroll
            for (int p = 0; p < 2; p++) {
                uint32_t t[4];
                ldm_x4(t, bB + bRow[p] + ((((kk << 1) + qhiB) ^ rowin) << 4));
                bv[2 * p][0] = t[0]; bv[2 * p][1] = t[1];
                bv[2 * p + 1][0] = t[2]; bv[2 * p + 1][1] = t[3];
            }
            #pragma unroll
            for (int mf = 0; mf < 4; mf++)
                #pragma unroll
                for (int nf = 0; nf < 4; nf++)
                    mma_bf16(acc[mf][nf], av[mf], bv[nf]);
        }
        __syncthreads();
    }

    // epilogue
    float rsum[4][2];
    if (SM_MODE == 1) {
        #pragma unroll
        for (int i = 0; i < 4; i++) { rsum[i][0] = 0.f; rsum[i][1] = 0.f; }
    }
    #pragma unroll
    for (int mf = 0; mf < 4; mf++) {
        #pragma unroll
        for (int half = 0; half < 2; half++) {
            int rw = bm + wm * 64 + mf * 16 + gr + half * 8;
            float bvv = (BIAS_MODE == 1) ? bias[rw] : 0.f;
            float zinv = 1.f;
            if (SM_MODE == 2) zinv = 1.f / Z[rw];
            #pragma unroll
            for (int nf = 0; nf < 4; nf++) {
                int cl = bn + wn * 32 + nf * 8 + t4 * 2;
                float ox = acc[mf][nf][half * 2 + 0] * alpha + bvv;
                float oy = acc[mf][nf][half * 2 + 1] * alpha + bvv;
                if (BIAS_MODE == 2) { ox += bias[cl]; oy += bias[cl + 1]; }
                if (HAS_SKIP) {
                    ox += skip[(size_t)cl * ldsk + rw];
                    oy += skip[(size_t)(cl + 1) * ldsk + rw];
                }
                if (SM_MODE == 1) {
                    ox = __expf(ox); oy = __expf(oy);
                    rsum[mf][half] += ox + oy;
                }
                if (SM_MODE == 2) { ox *= zinv; oy *= zinv; }
                if (OUT != 0)
                    *reinterpret_cast<float2*>(&Cf[(size_t)rw * ldc + cl]) =
                        make_float2(ox, oy);
                if (OUT != 1)
                    *reinterpret_cast<bf162*>(&Cb[(size_t)rw * ldc + cl]) =
                        __floats2bfloat162_rn(ox, oy);
            }
        }
    }

    if (SM_MODE == 1) {
        // reduce rsum across t4 quad, stash per-warp partials in smem, then
        // one atomicAdd per CTA row into Z.
        float* zs = reinterpret_cast<float*>(dsm);   // [128 rows][4 wn]
        __syncthreads();   // smem buffers no longer needed by mainloop
        #pragma unroll
        for (int mf = 0; mf < 4; mf++) {
            #pragma unroll
            for (int half = 0; half < 2; half++) {
                float s = rsum[mf][half];
                s += __shfl_xor_sync(0xffffffffu, s, 1);
                s += __shfl_xor_sync(0xffffffffu, s, 2);
                if (t4 == 0) {
                    int rloc = wm * 64 + mf * 16 + gr + half * 8;
                    zs[rloc * 4 + wn] = s;
                }
            }
        }
        __syncthreads();
        if (tid < 128) {
            float s = zs[tid * 4] + zs[tid * 4 + 1] + zs[tid * 4 + 2] + zs[tid * 4 + 3];
            atomicAdd(&Z[bm + tid], s);
        }
    }
}

// ---------------------------------------------------------------------------
// Launch
// ---------------------------------------------------------------------------
extern "C" void kernel_launch(void* const* d_in, const int* in_sizes, int n_in,
                              void* d_out, int out_size) {
    const float* x   = (const float*)d_in[0];
    const float* nsc = (const float*)d_in[1];
    const float* nbi = (const float*)d_in[2];
    const float* q_w = (const float*)d_in[3];
    const float* q_b = (const float*)d_in[4];
    const float* k_w = (const float*)d_in[5];
    const float* k_b = (const float*)d_in[6];
    const float* v_w = (const float*)d_in[7];
    const float* v_b = (const float*)d_in[8];
    const float* p_w = (const float*)d_in[9];
    const float* p_b = (const float*)d_in[10];
    float* out = (float*)d_out;

    bf16 *hntb, *hqb, *qtb, *ktb, *vb, *scb, *otb, *kwb, *vwb, *pwb, *qwb;
    float *qt, *Z;
    cudaGetSymbolAddress((void**)&hntb, gb_hnt);
    cudaGetSymbolAddress((void**)&hqb,  gb_hq);
    cudaGetSymbolAddress((void**)&qt,   g_qt);
    cudaGetSymbolAddress((void**)&qtb,  gb_qt);
    cudaGetSymbolAddress((void**)&ktb,  gb_kt);
    cudaGetSymbolAddress((void**)&vb,   gb_v);
    cudaGetSymbolAddress((void**)&scb,  gb_sc);
    cudaGetSymbolAddress((void**)&otb,  gb_ot);
    cudaGetSymbolAddress((void**)&kwb,  gb_kw);
    cudaGetSymbolAddress((void**)&vwb,  gb_vw);
    cudaGetSymbolAddress((void**)&pwb,  gb_pw);
    cudaGetSymbolAddress((void**)&qwb,  gb_qw);
    cudaGetSymbolAddress((void**)&Z,    g_Z);

    cudaFuncSetAttribute(mma_gemm<0, false, 0, 0>, cudaFuncAttributeMaxDynamicSharedMemorySize, GEMM_SMEM);
    cudaFuncSetAttribute(mma_gemm<0, false, 0, 1>, cudaFuncAttributeMaxDynamicSharedMemorySize, GEMM_SMEM);
    cudaFuncSetAttribute(mma_gemm<0, false, 0, 2>, cudaFuncAttributeMaxDynamicSharedMemorySize, GEMM_SMEM);
    cudaFuncSetAttribute(mma_gemm<1, false, 0, 0>, cudaFuncAttributeMaxDynamicSharedMemorySize, GEMM_SMEM);
    cudaFuncSetAttribute(mma_gemm<2, false, 0, 0>, cudaFuncAttributeMaxDynamicSharedMemorySize, GEMM_SMEM);
    cudaFuncSetAttribute(mma_gemm<2, false, 2, 0>, cudaFuncAttributeMaxDynamicSharedMemorySize, GEMM_SMEM);
    cudaFuncSetAttribute(mma_gemm<1, true,  1, 0>, cudaFuncAttributeMaxDynamicSharedMemorySize, GEMM_SMEM);

    const long long sHnt = (long long)N3 * C;
    const long long sHq  = (long long)HW * KQ;
    const long long sQt  = (long long)HW * C;
    const long long sKt  = (long long)N3 * C;
    const long long sV   = (long long)C * N3;
    const long long sSc  = (long long)HW * N3;
    const long long sOt  = (long long)HW * C;

    // GroupNorm (+ transpose) and weight conversion
    zero_kernel<<<(B * HW + 255) / 256, 256>>>();
    gn_stats_kernel<<<dim3(B * G, 16), 256>>>(x);
    gn_apply_t_kernel<<<dim3(HW / 32, C / 32, B * T), dim3(32, 8)>>>(x, nsc, nbi);
    wconv_kernel<<<(C * C + 255) / 256, 256>>>(k_w, v_w, p_w, q_w);

    // q (split-bf16 compensated, K=1536): qt[p][o] fp32 + bf16, + q_b[o]
    mma_gemm<2, false, 2, 0><<<dim3(HW / 128, C / 128, B), 256, GEMM_SMEM>>>(
        hqb, KQ, sHq, qwb, KQ, 0, qt, qtb, C, sQt, KQ, 1.f, q_b,
        nullptr, 0, 0, nullptr);

    // kt[m][o] = hnt[m][:] . k_w[o][:] + k_b[o]
    mma_gemm<2, false, 0, 0><<<dim3(N3 / 128, C / 128, B), 256, GEMM_SMEM>>>(
        hntb, C, sHnt, kwb, C, 0, nullptr, ktb, C, sKt, C, 1.f, k_b,
        nullptr, 0, 0, nullptr);

    // v[c][m] = v_w[c][:] . hnt[m][:] + v_b[c]
    mma_gemm<1, false, 0, 0><<<dim3(C / 128, N3 / 128, B), 256, GEMM_SMEM>>>(
        vwb, C, 0, hntb, C, sHnt, nullptr, vb, N3, sV, C, 1.f, v_b,
        nullptr, 0, 0, nullptr);

    // e[p][m] = exp((qt[p][:] . kt[m][:]) * C^-0.5); Z[p] += row sums
    mma_gemm<0, false, 0, 1><<<dim3(HW / 128, N3 / 128, B), 256, GEMM_SMEM>>>(
        qtb, C, sQt, ktb, C, sKt, nullptr, scb, N3, sSc, C,
        0.044194173824159216f, nullptr, nullptr, 0, 0, Z);

    // ot[p][c] = (e[p][:] . v[c][:]) / Z[p]
    mma_gemm<0, false, 0, 2><<<dim3(HW / 128, C / 128, B), 256, GEMM_SMEM>>>(
        scb, N3, sSc, vb, N3, sV, nullptr, otb, C, sOt, N3, 1.f,
        nullptr, nullptr, 0, 0, Z);

    // out[o][p] = p_w[o][:] . ot[p][:] + p_b[o] + qt[p][o]   (fp32 out)
    mma_gemm<1, true, 1, 0><<<dim3(C / 128, HW / 128, B), 256, GEMM_SMEM>>>(
        pwb, C, 0, otb, C, sOt, out, nullptr, HW, (long long)C * HW, C, 1.f, p_b,
        qt, C, sQt, nullptr);
}

// round 12
// speedup vs baseline: 1.3830x; 1.0009x over previous
#include <cuda_runtime.h>
#include <cuda_bf16.h>
#include <cstdint>

constexpr int B  = 4;
constexpr int C  = 512;
constexpr int T  = 3;
constexpr int HW = 2304;   // 48*48
constexpr int N3 = 6912;   // 3*HW
constexpr int G  = 4;
constexpr int CG = C / G;  // 128
constexpr int KQ = 3 * C;  // 1536: split-bf16 concat K for q
constexpr float EPS = 1e-6f;

typedef __nv_bfloat16  bf16;
typedef __nv_bfloat162 bf162;

// Scratch
__device__ bf16  gb_hnt[(size_t)B * N3 * C];   // normalized, transposed, bf16
__device__ bf16  gb_hq [(size_t)B * HW * KQ];  // t=1 slice split [hi|lo|hi]
__device__ float g_qt  [(size_t)B * HW * C];   // q fp32 (skip)
__device__ bf16  gb_qt [(size_t)B * HW * C];   // q bf16 (scores operand)
__device__ bf16  gb_kt [(size_t)B * N3 * C];   // k [m][c]
__device__ bf16  gb_v  [(size_t)B * C * N3];   // v [c][m]
__device__ bf16  gb_sc [(size_t)B * HW * N3];  // exp(scores) [p][m]
__device__ bf16  gb_ot [(size_t)B * HW * C];   // attn out [p][c]
__device__ bf16  gb_kw[C * C], gb_vw[C * C], gb_pw[C * C];
__device__ bf16  gb_qw[C * KQ];                // q weights split [hi|hi|lo]
__device__ float g_stats[2 * B * G];
__device__ float g_Z[(size_t)B * HW];          // softmax denominators

__device__ __forceinline__ uint32_t smem_u32(const void* p) {
    return (uint32_t)__cvta_generic_to_shared(p);
}
#define CP_ASYNC16(sm, gm) \
    asm volatile("cp.async.cg.shared.global [%0], [%1], 16;" :: "r"(sm), "l"(gm))
#define CP_COMMIT asm volatile("cp.async.commit_group;")
#define CP_WAIT1  asm volatile("cp.async.wait_group 1;")
#define CP_WAIT0  asm volatile("cp.async.wait_group 0;")

__device__ __forceinline__ void ldm_x4(uint32_t* r, uint32_t addr) {
    asm volatile("ldmatrix.sync.aligned.m8n8.x4.shared.b16 {%0,%1,%2,%3}, [%4];"
        : "=r"(r[0]), "=r"(r[1]), "=r"(r[2]), "=r"(r[3]) : "r"(addr));
}
__device__ __forceinline__ void mma_bf16(float* c, const uint32_t* a, const uint32_t* b) {
    asm volatile("mma.sync.aligned.m16n8k16.row.col.f32.bf16.bf16.f32 "
        "{%0,%1,%2,%3}, {%4,%5,%6,%7}, {%8,%9}, {%0,%1,%2,%3};"
        : "+f"(c[0]), "+f"(c[1]), "+f"(c[2]), "+f"(c[3])
        : "r"(a[0]), "r"(a[1]), "r"(a[2]), "r"(a[3]), "r"(b[0]), "r"(b[1]));
}

// ---------------------------------------------------------------------------
// Zero stats + Z
// ---------------------------------------------------------------------------
__global__ void zero_kernel() {
    int i = blockIdx.x * blockDim.x + threadIdx.x;
    if (i < B * HW) g_Z[i] = 0.f;
    if (i < 2 * B * G) g_stats[i] = 0.f;
}

__global__ void gn_stats_kernel(const float* __restrict__ x) {
    const int bg = blockIdx.x;
    const int b = bg >> 2, g = bg & 3;
    const int TOT4 = CG * T * HW / 4;
    const int PER  = TOT4 / 16;
    const int start = blockIdx.y * PER;

    float s = 0.f, ss = 0.f;
    for (int i = start + threadIdx.x; i < start + PER; i += blockDim.x) {
        int cl = i / (T * HW / 4);
        int r  = i - cl * (T * HW / 4);
        int t  = r / (HW / 4);
        int p4 = r - t * (HW / 4);
        float4 v = reinterpret_cast<const float4*>(x)[
            ((size_t)(t * B + b) * C + g * CG + cl) * (HW / 4) + p4];
        s  += v.x + v.y + v.z + v.w;
        ss += v.x * v.x + v.y * v.y + v.z * v.z + v.w * v.w;
    }
    __shared__ float rs[8], rss[8];
    #pragma unroll
    for (int o = 16; o; o >>= 1) {
        s  += __shfl_xor_sync(0xffffffffu, s, o);
        ss += __shfl_xor_sync(0xffffffffu, ss, o);
    }
    if ((threadIdx.x & 31) == 0) { rs[threadIdx.x >> 5] = s; rss[threadIdx.x >> 5] = ss; }
    __syncthreads();
    if (threadIdx.x == 0) {
        float a = 0.f, c = 0.f;
        #pragma unroll
        for (int i = 0; i < 8; i++) { a += rs[i]; c += rss[i]; }
        atomicAdd(&g_stats[2 * bg],     a);
        atomicAdd(&g_stats[2 * bg + 1], c);
    }
}

// normalize + affine + transpose -> gb_hnt (bf16); t=1 slice split hi/lo
__global__ void gn_apply_t_kernel(const float* __restrict__ x,
                                  const float* __restrict__ scale,
                                  const float* __restrict__ bias) {
    __shared__ float tile[32][33];
    const int bt = blockIdx.z;
    const int b = bt / T, t = bt - b * T;
    const int p0 = blockIdx.x << 5, c0 = blockIdx.y << 5;
    const int tx = threadIdx.x, ty = threadIdx.y;  // 32 x 8
    const float nrm = 1.f / (float)(CG * T * HW);

    #pragma unroll
    for (int kk = 0; kk < 4; kk++) {
        int c = c0 + ty + kk * 8;
        int g = c >> 7;
        float sum = g_stats[2 * (b * G + g)];
        float sq  = g_stats[2 * (b * G + g) + 1];
        float mean = sum * nrm;
        float var  = sq * nrm - mean * mean;
        float rstd = rsqrtf(var + EPS);
        float a = rstd * scale[c];
        float d = bias[c] - mean * a;
        float v = x[((size_t)(t * B + b) * C + c) * HW + p0 + tx];
        tile[ty + kk * 8][tx] = v * a + d;
    }
    __syncthreads();
    #pragma unroll
    for (int kk = 0; kk < 4; kk++) {
        int p = p0 + ty + kk * 8;
        float v = tile[tx][ty + kk * 8];
        bf16 hi = __float2bfloat16(v);
        gb_hnt[(size_t)b * N3 * C + (size_t)(t * HW + p) * C + c0 + tx] = hi;
        if (t == 1) {
            bf16 lo = __float2bfloat16(v - __bfloat162float(hi));
            size_t base = ((size_t)b * HW + p) * KQ + c0 + tx;
            gb_hq[base]            = hi;
            gb_hq[base + C]        = lo;
            gb_hq[base + 2 * C]    = hi;
        }
    }
}

// Convert weights: k/v/p to bf16; q to split [hi|hi|lo] layout
__global__ void wconv_kernel(const float* __restrict__ kw,
                             const float* __restrict__ vw,
                             const float* __restrict__ pw,
                             const float* __restrict__ qw) {
    int i = blockIdx.x * blockDim.x + threadIdx.x;
    if (i < C * C) {
        gb_kw[i] = __float2bfloat16(kw[i]);
        gb_vw[i] = __float2bfloat16(vw[i]);
        gb_pw[i] = __float2bfloat16(pw[i]);
        float w = qw[i];
        bf16 hi = __float2bfloat16(w);
        bf16 lo = __float2bfloat16(w - __bfloat162float(hi));
        int o = i / C, c = i - o * C;
        gb_qw[(size_t)o * KQ + c]         = hi;
        gb_qw[(size_t)o * KQ + C + c]     = hi;
        gb_qw[(size_t)o * KQ + 2 * C + c] = lo;
    }
}

// ---------------------------------------------------------------------------
// BF16 mma.sync GEMM: 128x128 tile, BK=64, 8 warps (2x4), warp 64x32,
// m16n8k16, 2-stage cp.async, quad-XOR swizzle.
// C[m,n] = alpha * sum_k A[m,k]*Bm[n,k] (+bias) (+skip^T). K-major operands.
// BIAS_MODE: 0 none, 1 bias[row m], 2 bias[col n].
// OUT: 0 = bf16 -> Cb, 1 = fp32 -> Cf, 2 = both.
// SM_MODE: 0 none, 1 = exp + row-sum atomics into Z (scores),
//          2 = scale output rows by 1/Z[row] (attn*V).
// ---------------------------------------------------------------------------
constexpr int GEMM_SMEM = 2 * 2 * 128 * 128;   // 65536 bytes

template <int BIAS_MODE, bool HAS_SKIP, int OUT, int SM_MODE>
__global__ __launch_bounds__(256, 2)
void mma_gemm(const bf16* __restrict__ A, int lda, long long sA,
              const bf16* __restrict__ Bm, int ldb, long long sB,
              float* __restrict__ Cf, bf16* __restrict__ Cb, int ldc, long long sC,
              int K, float alpha, const float* __restrict__ bias,
              const float* __restrict__ skip, int ldsk, long long sSk,
              float* __restrict__ Z) {
    extern __shared__ __align__(16) char dsm[];

    const int bz = blockIdx.z;
    A  += (size_t)bz * sA;
    Bm += (size_t)bz * sB;
    if (OUT != 0) Cf += (size_t)bz * sC;
    if (OUT != 1) Cb += (size_t)bz * sC;
    if (HAS_SKIP) skip += (size_t)bz * sSk;
    if (SM_MODE != 0) Z += (size_t)bz * HW;

    const int bm = blockIdx.x * 128, bn = blockIdx.y * 128;
    const int tid = threadIdx.x, wid = tid >> 5, lane = tid & 31;
    const int wm = wid & 1, wn = wid >> 1;      // warp grid 2 (M) x 4 (N)
    const int gr = lane >> 2, t4 = lane & 3;
    const int grp = lane >> 3, rowin = lane & 7;
    const int qhiA = grp >> 1;
    const int qhiB = grp & 1;

    // staging: thread -> row r = tid>>1, 16B chunks q0..q0+3 of that row
    const int r  = tid >> 1;
    const int q0 = (tid & 1) * 4;
    const bf16* Arow = A  + (size_t)(bm + r) * lda;
    const bf16* Brow = Bm + (size_t)(bn + r) * ldb;
    uint32_t off[4];
    #pragma unroll
    for (int j = 0; j < 4; j++)
        off[j] = r * 128 + (((q0 + j) ^ (r & 7)) << 4);   // bytes within 16KB tile
    const uint32_t smBase = smem_u32(dsm);
    // layout: [buf0 A | buf0 B | buf1 A | buf1 B], 16KB each
    auto stage = [&](int k0, int buf) {
        uint32_t ab = smBase + buf * 32768;
        uint32_t bb = ab + 16384;
        #pragma unroll
        for (int j = 0; j < 4; j++) {
            CP_ASYNC16(ab + off[j], Arow + k0 + (q0 + j) * 8);
            CP_ASYNC16(bb + off[j], Brow + k0 + (q0 + j) * 8);
        }
        CP_COMMIT;
    };

    // fragment row byte-offsets
    uint32_t aRow[4], bRow[2];
    #pragma unroll
    for (int mf = 0; mf < 4; mf++)
        aRow[mf] = (uint32_t)(wm * 64 + mf * 16 + (grp & 1) * 8 + rowin) * 128;
    #pragma unroll
    for (int p = 0; p < 2; p++)
        bRow[p] = (uint32_t)(wn * 32 + p * 16 + (grp >> 1) * 8 + rowin) * 128;

    float acc[4][4][4];
    #pragma unroll
    for (int i = 0; i < 4; i++)
        #pragma unroll
        for (int j = 0; j < 4; j++)
            #pragma unroll
            for (int q = 0; q < 4; q++) acc[i][j][q] = 0.f;

    const int nk = K >> 6;                      // BK = 64 bf16
    stage(0, 0);
    for (int kt = 0; kt < nk; kt++) {
        if (kt + 1 < nk) { stage((kt + 1) << 6, (kt + 1) & 1); CP_WAIT1; }
        else             { CP_WAIT0; }
        __syncthreads();
        const uint32_t aB = smBase + (kt & 1) * 32768;
        const uint32_t bB = aB + 16384;
        #pragma unroll
        for (int kk = 0; kk < 4; kk++) {        // 4 x K16 per tile
            uint32_t av[4][4], bv[4][2];
            #pragma unroll
            for (int mf = 0; mf < 4; mf++)
                ldm_x4(av[mf], aB + aRow[mf] + ((((kk << 1) + qhiA) ^ rowin) << 4));
            #pragma unroll
            for (int p = 0; p < 2; p++) {
                uint32_t t[4];
                ldm_x4(t, bB + bRow[p] + ((((kk << 1) + qhiB) ^ rowin) << 4));
                bv[2 * p][0] = t[0]; bv[2 * p][1] = t[1];
                bv[2 * p + 1][0] = t[2]; bv[2 * p + 1][1] = t[3];
            }
            #pragma unroll
            for (int mf = 0; mf < 4; mf++)
                #pragma unroll
                for (int nf = 0; nf < 4; nf++)
                    mma_bf16(acc[mf][nf], av[mf], bv[nf]);
        }
        __syncthreads();
    }

    // epilogue
    float rsum[4][2];
    if (SM_MODE == 1) {
        #pragma unroll
        for (int i = 0; i < 4; i++) { rsum[i][0] = 0.f; rsum[i][1] = 0.f; }
    }
    #pragma unroll
    for (int mf = 0; mf < 4; mf++) {
        #pragma unroll
        for (int half = 0; half < 2; half++) {
            int rw = bm + wm * 64 + mf * 16 + gr + half * 8;
            float bvv = (BIAS_MODE == 1) ? bias[rw] : 0.f;
            float zinv = 1.f;
            if (SM_MODE == 2) zinv = 1.f / Z[rw];
            #pragma unroll
            for (int nf = 0; nf < 4; nf++) {
                int cl = bn + wn * 32 + nf * 8 + t4 * 2;
                float ox = acc[mf][nf][half * 2 + 0] * alpha + bvv;
                float oy = acc[mf][nf][half * 2 + 1] * alpha + bvv;
                if (BIAS_MODE == 2) { ox += bias[cl]; oy += bias[cl + 1]; }
                if (HAS_SKIP) {
                    ox += skip[(size_t)cl * ldsk + rw];
                    oy += skip[(size_t)(cl + 1) * ldsk + rw];
                }
                if (SM_MODE == 1) {
                    ox = __expf(ox); oy = __expf(oy);
                    rsum[mf][half] += ox + oy;
                }
                if (SM_MODE == 2) { ox *= zinv; oy *= zinv; }
                if (OUT != 0)
                    *reinterpret_cast<float2*>(&Cf[(size_t)rw * ldc + cl]) =
                        make_float2(ox, oy);
                if (OUT != 1)
                    *reinterpret_cast<bf162*>(&Cb[(size_t)rw * ldc + cl]) =
                        __floats2bfloat162_rn(ox, oy);
            }
        }
    }

    if (SM_MODE == 1) {
        // reduce rsum across t4 quad, stash per-warp partials in smem, then
        // one atomicAdd per CTA row into Z.
        float* zs = reinterpret_cast<float*>(dsm);   // [128 rows][4 wn]
        __syncthreads();   // smem buffers no longer needed by mainloop
        #pragma unroll
        for (int mf = 0; mf < 4; mf++) {
            #pragma unroll
            for (int half = 0; half < 2; half++) {
                float s = rsum[mf][half];
                s += __shfl_xor_sync(0xffffffffu, s, 1);
                s += __shfl_xor_sync(0xffffffffu, s, 2);
                if (t4 == 0) {
                    int rloc = wm * 64 + mf * 16 + gr + half * 8;
                    zs[rloc * 4 + wn] = s;
                }
            }
        }
        __syncthreads();
        if (tid < 128) {
            float s = zs[tid * 4] + zs[tid * 4 + 1] + zs[tid * 4 + 2] + zs[tid * 4 + 3];
            atomicAdd(&Z[bm + tid], s);
        }
    }
}

// ---------------------------------------------------------------------------
// Launch
// ---------------------------------------------------------------------------
extern "C" void kernel_launch(void* const* d_in, const int* in_sizes, int n_in,
                              void* d_out, int out_size) {
    const float* x   = (const float*)d_in[0];
    const float* nsc = (const float*)d_in[1];
    const float* nbi = (const float*)d_in[2];
    const float* q_w = (const float*)d_in[3];
    const float* q_b = (const float*)d_in[4];
    const float* k_w = (const float*)d_in[5];
    const float* k_b = (const float*)d_in[6];
    const float* v_w = (const float*)d_in[7];
    const float* v_b = (const float*)d_in[8];
    const float* p_w = (const float*)d_in[9];
    const float* p_b = (const float*)d_in[10];
    float* out = (float*)d_out;

    bf16 *hntb, *hqb, *qtb, *ktb, *vb, *scb, *otb, *kwb, *vwb, *pwb, *qwb;
    float *qt, *Z;
    cudaGetSymbolAddress((void**)&hntb, gb_hnt);
    cudaGetSymbolAddress((void**)&hqb,  gb_hq);
    cudaGetSymbolAddress((void**)&qt,   g_qt);
    cudaGetSymbolAddress((void**)&qtb,  gb_qt);
    cudaGetSymbolAddress((void**)&ktb,  gb_kt);
    cudaGetSymbolAddress((void**)&vb,   gb_v);
    cudaGetSymbolAddress((void**)&scb,  gb_sc);
    cudaGetSymbolAddress((void**)&otb,  gb_ot);
    cudaGetSymbolAddress((void**)&kwb,  gb_kw);
    cudaGetSymbolAddress((void**)&vwb,  gb_vw);
    cudaGetSymbolAddress((void**)&pwb,  gb_pw);
    cudaGetSymbolAddress((void**)&qwb,  gb_qw);
    cudaGetSymbolAddress((void**)&Z,    g_Z);

    cudaFuncSetAttribute(mma_gemm<0, false, 0, 0>, cudaFuncAttributeMaxDynamicSharedMemorySize, GEMM_SMEM);
    cudaFuncSetAttribute(mma_gemm<0, false, 0, 1>, cudaFuncAttributeMaxDynamicSharedMemorySize, GEMM_SMEM);
    cudaFuncSetAttribute(mma_gemm<0, false, 0, 2>, cudaFuncAttributeMaxDynamicSharedMemorySize, GEMM_SMEM);
    cudaFuncSetAttribute(mma_gemm<1, false, 0, 0>, cudaFuncAttributeMaxDynamicSharedMemorySize, GEMM_SMEM);
    cudaFuncSetAttribute(mma_gemm<2, false, 0, 0>, cudaFuncAttributeMaxDynamicSharedMemorySize, GEMM_SMEM);
    cudaFuncSetAttribute(mma_gemm<2, false, 2, 0>, cudaFuncAttributeMaxDynamicSharedMemorySize, GEMM_SMEM);
    cudaFuncSetAttribute(mma_gemm<1, true,  1, 0>, cudaFuncAttributeMaxDynamicSharedMemorySize, GEMM_SMEM);

    const long long sHnt = (long long)N3 * C;
    const long long sHq  = (long long)HW * KQ;
    const long long sQt  = (long long)HW * C;
    const long long sKt  = (long long)N3 * C;
    const long long sV   = (long long)C * N3;
    const long long sSc  = (long long)HW * N3;
    const long long sOt  = (long long)HW * C;

    // GroupNorm (+ transpose) and weight conversion
    zero_kernel<<<(B * HW + 255) / 256, 256>>>();
    gn_stats_kernel<<<dim3(B * G, 16), 256>>>(x);
    gn_apply_t_kernel<<<dim3(HW / 32, C / 32, B * T), dim3(32, 8)>>>(x, nsc, nbi);
    wconv_kernel<<<(C * C + 255) / 256, 256>>>(k_w, v_w, p_w, q_w);

    // q (split-bf16 compensated, K=1536): qt[p][o] fp32 + bf16, + q_b[o]
    mma_gemm<2, false, 2, 0><<<dim3(HW / 128, C / 128, B), 256, GEMM_SMEM>>>(
        hqb, KQ, sHq, qwb, KQ, 0, qt, qtb, C, sQt, KQ, 1.f, q_b,
        nullptr, 0, 0, nullptr);

    // kt[m][o] = hnt[m][:] . k_w[o][:] + k_b[o]
    mma_gemm<2, false, 0, 0><<<dim3(N3 / 128, C / 128, B), 256, GEMM_SMEM>>>(
        hntb, C, sHnt, kwb, C, 0, nullptr, ktb, C, sKt, C, 1.f, k_b,
        nullptr, 0, 0, nullptr);

    // v[c][m] = v_w[c][:] . hnt[m][:] + v_b[c]
    mma_gemm<1, false, 0, 0><<<dim3(C / 128, N3 / 128, B), 256, GEMM_SMEM>>>(
        vwb, C, 0, hntb, C, sHnt, nullptr, vb, N3, sV, C, 1.f, v_b,
        nullptr, 0, 0, nullptr);

    // e[p][m] = exp((qt[p][:] . kt[m][:]) * C^-0.5); Z[p] += row sums
    mma_gemm<0, false, 0, 1><<<dim3(HW / 128, N3 / 128, B), 256, GEMM_SMEM>>>(
        qtb, C, sQt, ktb, C, sKt, nullptr, scb, N3, sSc, C,
        0.044194173824159216f, nullptr, nullptr, 0, 0, Z);

    // ot[p][c] = (e[p][:] . v[c][:]) / Z[p]
    mma_gemm<0, false, 0, 2><<<dim3(HW / 128, C / 128, B), 256, GEMM_SMEM>>>(
        scb, N3, sSc, vb, N3, sV, nullptr, otb, C, sOt, N3, 1.f,
        nullptr, nullptr, 0, 0, Z);

    // out[o][p] = p_w[o][:] . ot[p][:] + p_b[o] + qt[p][o]   (fp32 out)
    mma_gemm<1, true, 1, 0><<<dim3(C / 128, HW / 128, B), 256, GEMM_SMEM>>>(
        pwb, C, 0, otb, C, sOt, out, nullptr, HW, (long long)C * HW, C, 1.f, p_b,
        qt, C, sQt, nullptr);
}

// round 13
// speedup vs baseline: 1.4216x; 1.0279x over previous
#include <cuda_runtime.h>
#include <cuda_bf16.h>
#include <cstdint>

constexpr int B  = 4;
constexpr int C  = 512;
constexpr int T  = 3;
constexpr int HW = 2304;   // 48*48
constexpr int N3 = 6912;   // 3*HW
constexpr int G  = 4;
constexpr int CG = C / G;  // 128
constexpr int KQ = 3 * C;  // 1536: split-bf16 concat K for q
constexpr float EPS = 1e-6f;

typedef __nv_bfloat16  bf16;
typedef __nv_bfloat162 bf162;

// Scratch
__device__ bf16  gb_hnt[(size_t)B * N3 * C];   // normalized, transposed, bf16
__device__ bf16  gb_hq [(size_t)B * HW * KQ];  // t=1 slice split [hi|lo|hi]
__device__ float g_qt  [(size_t)B * HW * C];   // q fp32 (skip)
__device__ bf16  gb_qt [(size_t)B * HW * C];   // q bf16 (scores operand)
__device__ bf16  gb_kt [(size_t)B * N3 * C];   // k [m][c]
__device__ bf16  gb_v  [(size_t)B * C * N3];   // v [c][m]
__device__ bf16  gb_sc [(size_t)B * HW * N3];  // exp(scores) [p][m]
__device__ bf16  gb_ot [(size_t)B * HW * C];   // attn out [p][c]
__device__ bf16  gb_kw[C * C], gb_vw[C * C], gb_pw[C * C];
__device__ bf16  gb_qw[C * KQ];                // q weights split [hi|hi|lo]
__device__ float g_stats[2 * B * G];
__device__ float g_Z[(size_t)B * HW];          // softmax denominators

__device__ __forceinline__ uint32_t smem_u32(const void* p) {
    return (uint32_t)__cvta_generic_to_shared(p);
}
#define CP_ASYNC16(sm, gm) \
    asm volatile("cp.async.cg.shared.global [%0], [%1], 16;" :: "r"(sm), "l"(gm))
#define CP_COMMIT asm volatile("cp.async.commit_group;")
#define CP_WAIT1  asm volatile("cp.async.wait_group 1;")
#define CP_WAIT0  asm volatile("cp.async.wait_group 0;")

__device__ __forceinline__ void ldm_x4(uint32_t* r, uint32_t addr) {
    asm volatile("ldmatrix.sync.aligned.m8n8.x4.shared.b16 {%0,%1,%2,%3}, [%4];"
        : "=r"(r[0]), "=r"(r[1]), "=r"(r[2]), "=r"(r[3]) : "r"(addr));
}
__device__ __forceinline__ void mma_bf16(float* c, const uint32_t* a, const uint32_t* b) {
    asm volatile("mma.sync.aligned.m16n8k16.row.col.f32.bf16.bf16.f32 "
        "{%0,%1,%2,%3}, {%4,%5,%6,%7}, {%8,%9}, {%0,%1,%2,%3};"
        : "+f"(c[0]), "+f"(c[1]), "+f"(c[2]), "+f"(c[3])
        : "r"(a[0]), "r"(a[1]), "r"(a[2]), "r"(a[3]), "r"(b[0]), "r"(b[1]));
}

// ---------------------------------------------------------------------------
// GroupNorm stats
// ---------------------------------------------------------------------------
__global__ void gn_stats_kernel(const float* __restrict__ x) {
    const int bg = blockIdx.x;
    const int b = bg >> 2, g = bg & 3;
    const int TOT4 = CG * T * HW / 4;
    const int PER  = TOT4 / 16;
    const int start = blockIdx.y * PER;

    float s = 0.f, ss = 0.f;
    for (int i = start + threadIdx.x; i < start + PER; i += blockDim.x) {
        int cl = i / (T * HW / 4);
        int r  = i - cl * (T * HW / 4);
        int t  = r / (HW / 4);
        int p4 = r - t * (HW / 4);
        float4 v = reinterpret_cast<const float4*>(x)[
            ((size_t)(t * B + b) * C + g * CG + cl) * (HW / 4) + p4];
        s  += v.x + v.y + v.z + v.w;
        ss += v.x * v.x + v.y * v.y + v.z * v.z + v.w * v.w;
    }
    __shared__ float rs[8], rss[8];
    #pragma unroll
    for (int o = 16; o; o >>= 1) {
        s  += __shfl_xor_sync(0xffffffffu, s, o);
        ss += __shfl_xor_sync(0xffffffffu, ss, o);
    }
    if ((threadIdx.x & 31) == 0) { rs[threadIdx.x >> 5] = s; rss[threadIdx.x >> 5] = ss; }
    __syncthreads();
    if (threadIdx.x == 0) {
        float a = 0.f, c = 0.f;
        #pragma unroll
        for (int i = 0; i < 8; i++) { a += rs[i]; c += rss[i]; }
        atomicAdd(&g_stats[2 * bg],     a);
        atomicAdd(&g_stats[2 * bg + 1], c);
    }
}

// normalize + affine + transpose -> gb_hnt (bf16); t=1 slice split hi/lo
__global__ void gn_apply_t_kernel(const float* __restrict__ x,
                                  const float* __restrict__ scale,
                                  const float* __restrict__ bias) {
    __shared__ float tile[32][33];
    const int bt = blockIdx.z;
    const int b = bt / T, t = bt - b * T;
    const int p0 = blockIdx.x << 5, c0 = blockIdx.y << 5;
    const int tx = threadIdx.x, ty = threadIdx.y;  // 32 x 8
    const float nrm = 1.f / (float)(CG * T * HW);

    #pragma unroll
    for (int kk = 0; kk < 4; kk++) {
        int c = c0 + ty + kk * 8;
        int g = c >> 7;
        float sum = g_stats[2 * (b * G + g)];
        float sq  = g_stats[2 * (b * G + g) + 1];
        float mean = sum * nrm;
        float var  = sq * nrm - mean * mean;
        float rstd = rsqrtf(var + EPS);
        float a = rstd * scale[c];
        float d = bias[c] - mean * a;
        float v = x[((size_t)(t * B + b) * C + c) * HW + p0 + tx];
        tile[ty + kk * 8][tx] = v * a + d;
    }
    __syncthreads();
    #pragma unroll
    for (int kk = 0; kk < 4; kk++) {
        int p = p0 + ty + kk * 8;
        float v = tile[tx][ty + kk * 8];
        bf16 hi = __float2bfloat16(v);
        gb_hnt[(size_t)b * N3 * C + (size_t)(t * HW + p) * C + c0 + tx] = hi;
        if (t == 1) {
            bf16 lo = __float2bfloat16(v - __bfloat162float(hi));
            size_t base = ((size_t)b * HW + p) * KQ + c0 + tx;
            gb_hq[base]            = hi;
            gb_hq[base + C]        = lo;
            gb_hq[base + 2 * C]    = hi;
        }
    }
}

// Convert weights + zero Z/stats (merged prep kernel)
__global__ void prep_kernel(const float* __restrict__ kw,
                            const float* __restrict__ vw,
                            const float* __restrict__ pw,
                            const float* __restrict__ qw) {
    int i = blockIdx.x * blockDim.x + threadIdx.x;
    if (i < B * HW) g_Z[i] = 0.f;
    if (i < 2 * B * G) g_stats[i] = 0.f;
    if (i < C * C) {
        gb_kw[i] = __float2bfloat16(kw[i]);
        gb_vw[i] = __float2bfloat16(vw[i]);
        gb_pw[i] = __float2bfloat16(pw[i]);
        float w = qw[i];
        bf16 hi = __float2bfloat16(w);
        bf16 lo = __float2bfloat16(w - __bfloat162float(hi));
        int o = i / C, c = i - o * C;
        gb_qw[(size_t)o * KQ + c]         = hi;
        gb_qw[(size_t)o * KQ + C + c]     = hi;
        gb_qw[(size_t)o * KQ + 2 * C + c] = lo;
    }
}

// ---------------------------------------------------------------------------
// BF16 mma.sync GEMM: 128x128 tile, BK=64, 8 warps (2x4), warp 64x32,
// m16n8k16, 3-stage cp.async ring, ONE __syncthreads per K-tile,
// quad-XOR swizzle.
// C[m,n] = alpha * sum_k A[m,k]*Bm[n,k] (+bias) (+skip^T). K-major operands.
// BIAS_MODE: 0 none, 1 bias[row m], 2 bias[col n].
// OUT: 0 = bf16 -> Cb, 1 = fp32 -> Cf, 2 = both.
// SM_MODE: 0 none, 1 = exp + row-sum atomics into Z (scores),
//          2 = scale output rows by 1/Z[row] (attn*V).
// ---------------------------------------------------------------------------
constexpr int STAGE_BYTES = 2 * 128 * 128;     // A tile + B tile = 32 KB
constexpr int GEMM_SMEM = 3 * STAGE_BYTES;     // 98304 bytes

template <int BIAS_MODE, bool HAS_SKIP, int OUT, int SM_MODE>
__global__ __launch_bounds__(256, 2)
void mma_gemm(const bf16* __restrict__ A, int lda, long long sA,
              const bf16* __restrict__ Bm, int ldb, long long sB,
              float* __restrict__ Cf, bf16* __restrict__ Cb, int ldc, long long sC,
              int K, float alpha, const float* __restrict__ bias,
              const float* __restrict__ skip, int ldsk, long long sSk,
              float* __restrict__ Z) {
    extern __shared__ __align__(16) char dsm[];

    const int bz = blockIdx.z;
    A  += (size_t)bz * sA;
    Bm += (size_t)bz * sB;
    if (OUT != 0) Cf += (size_t)bz * sC;
    if (OUT != 1) Cb += (size_t)bz * sC;
    if (HAS_SKIP) skip += (size_t)bz * sSk;
    if (SM_MODE != 0) Z += (size_t)bz * HW;

    const int bm = blockIdx.x * 128, bn = blockIdx.y * 128;
    const int tid = threadIdx.x, wid = tid >> 5, lane = tid & 31;
    const int wm = wid & 1, wn = wid >> 1;      // warp grid 2 (M) x 4 (N)
    const int gr = lane >> 2, t4 = lane & 3;
    const int grp = lane >> 3, rowin = lane & 7;
    const int qhiA = grp >> 1;
    const int qhiB = grp & 1;

    // staging: thread -> row r = tid>>1, 16B chunks q0..q0+3 of that row
    const int r  = tid >> 1;
    const int q0 = (tid & 1) * 4;
    const bf16* Arow = A  + (size_t)(bm + r) * lda;
    const bf16* Brow = Bm + (size_t)(bn + r) * ldb;
    uint32_t off[4];
    #pragma unroll
    for (int j = 0; j < 4; j++)
        off[j] = r * 128 + (((q0 + j) ^ (r & 7)) << 4);   // bytes within 16KB tile
    const uint32_t smBase = smem_u32(dsm);
    // stage s at smBase + s*32KB: [A 16KB | B 16KB]
    auto stage = [&](int k0, int s) {
        uint32_t ab = smBase + s * STAGE_BYTES;
        uint32_t bb = ab + 16384;
        #pragma unroll
        for (int j = 0; j < 4; j++) {
            CP_ASYNC16(ab + off[j], Arow + k0 + (q0 + j) * 8);
            CP_ASYNC16(bb + off[j], Brow + k0 + (q0 + j) * 8);
        }
        CP_COMMIT;
    };

    // fragment row byte-offsets
    uint32_t aRow[4], bRow[2];
    #pragma unroll
    for (int mf = 0; mf < 4; mf++)
        aRow[mf] = (uint32_t)(wm * 64 + mf * 16 + (grp & 1) * 8 + rowin) * 128;
    #pragma unroll
    for (int p = 0; p < 2; p++)
        bRow[p] = (uint32_t)(wn * 32 + p * 16 + (grp >> 1) * 8 + rowin) * 128;

    float acc[4][4][4];
    #pragma unroll
    for (int i = 0; i < 4; i++)
        #pragma unroll
        for (int j = 0; j < 4; j++)
            #pragma unroll
            for (int q = 0; q < 4; q++) acc[i][j][q] = 0.f;

    const int nk = K >> 6;                      // BK = 64 bf16
    stage(0, 0);
    stage(64, 1);

    int s_cur = 0, s_nxt = 2;
    for (int kt = 0; kt < nk; kt++) {
        if (kt == nk - 1) { CP_WAIT0; } else { CP_WAIT1; }
        __syncthreads();
        if (kt + 2 < nk) stage((kt + 2) << 6, s_nxt);
        const uint32_t aB = smBase + s_cur * STAGE_BYTES;
        const uint32_t bB = aB + 16384;
        #pragma unroll
        for (int kk = 0; kk < 4; kk++) {        // 4 x K16 per tile
            uint32_t av[4][4], bv[4][2];
            #pragma unroll
            for (int mf = 0; mf < 4; mf++)
                ldm_x4(av[mf], aB + aRow[mf] + ((((kk << 1) + qhiA) ^ rowin) << 4));
            #pragma unroll
            for (int p = 0; p < 2; p++) {
                uint32_t t[4];
                ldm_x4(t, bB + bRow[p] + ((((kk << 1) + qhiB) ^ rowin) << 4));
                bv[2 * p][0] = t[0]; bv[2 * p][1] = t[1];
                bv[2 * p + 1][0] = t[2]; bv[2 * p + 1][1] = t[3];
            }
            #pragma unroll
            for (int mf = 0; mf < 4; mf++)
                #pragma unroll
                for (int nf = 0; nf < 4; nf++)
                    mma_bf16(acc[mf][nf], av[mf], bv[nf]);
        }
        s_cur = (s_cur + 1) % 3;
        s_nxt = (s_nxt + 1) % 3;
    }

    // epilogue
    float rsum[4][2];
    if (SM_MODE == 1) {
        #pragma unroll
        for (int i = 0; i < 4; i++) { rsum[i][0] = 0.f; rsum[i][1] = 0.f; }
    }
    #pragma unroll
    for (int mf = 0; mf < 4; mf++) {
        #pragma unroll
        for (int half = 0; half < 2; half++) {
            int rw = bm + wm * 64 + mf * 16 + gr + half * 8;
            float bvv = (BIAS_MODE == 1) ? bias[rw] : 0.f;
            float zinv = 1.f;
            if (SM_MODE == 2) zinv = 1.f / Z[rw];
            #pragma unroll
            for (int nf = 0; nf < 4; nf++) {
                int cl = bn + wn * 32 + nf * 8 + t4 * 2;
                float ox = acc[mf][nf][half * 2 + 0] * alpha + bvv;
                float oy = acc[mf][nf][half * 2 + 1] * alpha + bvv;
                if (BIAS_MODE == 2) { ox += bias[cl]; oy += bias[cl + 1]; }
                if (HAS_SKIP) {
                    ox += skip[(size_t)cl * ldsk + rw];
                    oy += skip[(size_t)(cl + 1) * ldsk + rw];
                }
                if (SM_MODE == 1) {
                    ox = __expf(ox); oy = __expf(oy);
                    rsum[mf][half] += ox + oy;
                }
                if (SM_MODE == 2) { ox *= zinv; oy *= zinv; }
                if (OUT != 0)
                    *reinterpret_cast<float2*>(&Cf[(size_t)rw * ldc + cl]) =
                        make_float2(ox, oy);
                if (OUT != 1)
                    *reinterpret_cast<bf162*>(&Cb[(size_t)rw * ldc + cl]) =
                        __floats2bfloat162_rn(ox, oy);
            }
        }
    }

    if (SM_MODE == 1) {
        // reduce rsum across t4 quad, stash per-warp partials in smem, then
        // one atomicAdd per CTA row into Z.
        float* zs = reinterpret_cast<float*>(dsm);   // [128 rows][4 wn]
        __syncthreads();   // smem buffers no longer needed by mainloop
        #pragma unroll
        for (int mf = 0; mf < 4; mf++) {
            #pragma unroll
            for (int half = 0; half < 2; half++) {
                float s = rsum[mf][half];
                s += __shfl_xor_sync(0xffffffffu, s, 1);
                s += __shfl_xor_sync(0xffffffffu, s, 2);
                if (t4 == 0) {
                    int rloc = wm * 64 + mf * 16 + gr + half * 8;
                    zs[rloc * 4 + wn] = s;
                }
            }
        }
        __syncthreads();
        if (tid < 128) {
            float s = zs[tid * 4] + zs[tid * 4 + 1] + zs[tid * 4 + 2] + zs[tid * 4 + 3];
            atomicAdd(&Z[bm + tid], s);
        }
    }
}

// ---------------------------------------------------------------------------
// Launch
// ---------------------------------------------------------------------------
extern "C" void kernel_launch(void* const* d_in, const int* in_sizes, int n_in,
                              void* d_out, int out_size) {
    const float* x   = (const float*)d_in[0];
    const float* nsc = (const float*)d_in[1];
    const float* nbi = (const float*)d_in[2];
    const float* q_w = (const float*)d_in[3];
    const float* q_b = (const float*)d_in[4];
    const float* k_w = (const float*)d_in[5];
    const float* k_b = (const float*)d_in[6];
    const float* v_w = (const float*)d_in[7];
    const float* v_b = (const float*)d_in[8];
    const float* p_w = (const float*)d_in[9];
    const float* p_b = (const float*)d_in[10];
    float* out = (float*)d_out;

    bf16 *hntb, *hqb, *qtb, *ktb, *vb, *scb, *otb, *kwb, *vwb, *pwb, *qwb;
    float *qt, *Z;
    cudaGetSymbolAddress((void**)&hntb, gb_hnt);
    cudaGetSymbolAddress((void**)&hqb,  gb_hq);
    cudaGetSymbolAddress((void**)&qt,   g_qt);
    cudaGetSymbolAddress((void**)&qtb,  gb_qt);
    cudaGetSymbolAddress((void**)&ktb,  gb_kt);
    cudaGetSymbolAddress((void**)&vb,   gb_v);
    cudaGetSymbolAddress((void**)&scb,  gb_sc);
    cudaGetSymbolAddress((void**)&otb,  gb_ot);
    cudaGetSymbolAddress((void**)&kwb,  gb_kw);
    cudaGetSymbolAddress((void**)&vwb,  gb_vw);
    cudaGetSymbolAddress((void**)&pwb,  gb_pw);
    cudaGetSymbolAddress((void**)&qwb,  gb_qw);
    cudaGetSymbolAddress((void**)&Z,    g_Z);

    cudaFuncSetAttribute(mma_gemm<0, false, 0, 1>, cudaFuncAttributeMaxDynamicSharedMemorySize, GEMM_SMEM);
    cudaFuncSetAttribute(mma_gemm<0, false, 0, 2>, cudaFuncAttributeMaxDynamicSharedMemorySize, GEMM_SMEM);
    cudaFuncSetAttribute(mma_gemm<1, false, 0, 0>, cudaFuncAttributeMaxDynamicSharedMemorySize, GEMM_SMEM);
    cudaFuncSetAttribute(mma_gemm<2, false, 0, 0>, cudaFuncAttributeMaxDynamicSharedMemorySize, GEMM_SMEM);
    cudaFuncSetAttribute(mma_gemm<2, false, 2, 0>, cudaFuncAttributeMaxDynamicSharedMemorySize, GEMM_SMEM);
    cudaFuncSetAttribute(mma_gemm<1, true,  1, 0>, cudaFuncAttributeMaxDynamicSharedMemorySize, GEMM_SMEM);

    const long long sHnt = (long long)N3 * C;
    const long long sHq  = (long long)HW * KQ;
    const long long sQt  = (long long)HW * C;
    const long long sKt  = (long long)N3 * C;
    const long long sV   = (long long)C * N3;
    const long long sSc  = (long long)HW * N3;
    const long long sOt  = (long long)HW * C;

    // Prep (zero + weight convert), GroupNorm (+ transpose)
    prep_kernel<<<(C * C + 255) / 256, 256>>>(k_w, v_w, p_w, q_w);
    gn_stats_kernel<<<dim3(B * G, 16), 256>>>(x);
    gn_apply_t_kernel<<<dim3(HW / 32, C / 32, B * T), dim3(32, 8)>>>(x, nsc, nbi);

    // q (split-bf16 compensated, K=1536): qt[p][o] fp32 + bf16, + q_b[o]
    mma_gemm<2, false, 2, 0><<<dim3(HW / 128, C / 128, B), 256, GEMM_SMEM>>>(
        hqb, KQ, sHq, qwb, KQ, 0, qt, qtb, C, sQt, KQ, 1.f, q_b,
        nullptr, 0, 0, nullptr);

    // kt[m][o] = hnt[m][:] . k_w[o][:] + k_b[o]
    mma_gemm<2, false, 0, 0><<<dim3(N3 / 128, C / 128, B), 256, GEMM_SMEM>>>(
        hntb, C, sHnt, kwb, C, 0, nullptr, ktb, C, sKt, C, 1.f, k_b,
        nullptr, 0, 0, nullptr);

    // v[c][m] = v_w[c][:] . hnt[m][:] + v_b[c]
    mma_gemm<1, false, 0, 0><<<dim3(C / 128, N3 / 128, B), 256, GEMM_SMEM>>>(
        vwb, C, 0, hntb, C, sHnt, nullptr, vb, N3, sV, C, 1.f, v_b,
        nullptr, 0, 0, nullptr);

    // e[p][m] = exp((qt[p][:] . kt[m][:]) * C^-0.5); Z[p] += row sums
    mma_gemm<0, false, 0, 1><<<dim3(HW / 128, N3 / 128, B), 256, GEMM_SMEM>>>(
        qtb, C, sQt, ktb, C, sKt, nullptr, scb, N3, sSc, C,
        0.044194173824159216f, nullptr, nullptr, 0, 0, Z);

    // ot[p][c] = (e[p][:] . v[c][:]) / Z[p]
    mma_gemm<0, false, 0, 2><<<dim3(HW / 128, C / 128, B), 256, GEMM_SMEM>>>(
        scb, N3, sSc, vb, N3, sV, nullptr, otb, C, sOt, N3, 1.f,
        nullptr, nullptr, 0, 0, Z);

    // out[o][p] = p_w[o][:] . ot[p][:] + p_b[o] + qt[p][o]   (fp32 out)
    mma_gemm<1, true, 1, 0><<<dim3(C / 128, HW / 128, B), 256, GEMM_SMEM>>>(
        pwb, C, 0, otb, C, sOt, out, nullptr, HW, (long long)C * HW, C, 1.f, p_b,
        qt, C, sQt, nullptr);
}